// round 1
// baseline (speedup 1.0000x reference)
#include <cuda_runtime.h>

namespace {
constexpr int BT  = 256;   // threads per block
constexpr int C   = 96;
constexpr int HW  = 56;
constexpr int SH  = 3;     // shift

// shared memory layout (in floats). Row strides chosen for bank-conflict
// freedom and 16B alignment of float4 loads (stride 100 => 400B rows).
constexpr int XW  = 0;               // window input / attn output : 56 x 100
constexpr int QO  = XW + 56 * 100;   // Q (pre-scaled)             : 56 x 100
constexpr int VO  = QO + 56 * 100;   // V                          : 56 x 100
constexpr int KO  = VO + 56 * 100;   // K^T                        : 96 x 51
constexpr int SO  = KO + 96 * 51;    // attention scores           : 56 x 56
constexpr int WO  = SO + 56 * 56;    // transposed weight tile     : 96 x 97
constexpr int SMF = WO + 96 * 97;    // total floats (34144 = 133.4 KiB)
}

__global__ void __launch_bounds__(BT, 1)
swin_fused(const float* __restrict__ x,
           const float* __restrict__ ln_g, const float* __restrict__ ln_b,
           const float* __restrict__ qkv_w, const float* __restrict__ qkv_b,
           const float* __restrict__ proj_w, const float* __restrict__ proj_b,
           const float* __restrict__ rel_table,
           float* __restrict__ out)
{
    extern __shared__ float sm[];
    __shared__ int scnt[49];

    const int tid  = threadIdx.x;
    const int lane = tid & 31;
    const int wrp  = tid >> 5;

    const int wid = blockIdx.x;
    const int b   = wid >> 6;
    const int w64 = wid & 63;
    const int wy  = w64 >> 3;
    const int wx  = w64 & 7;
    const float* xb = x + (size_t)b * C * HW * HW;

    // shift-mask region id per window position (analytic form of _shift_mask):
    // regions only differ inside the last window row/col (wy==7 / wx==7);
    // slices (-7,-3) -> local idx 0..3 region 1, (-3,None) -> 4..6 region 2.
    if (tid < 49) {
        int iy = tid / 7, ix = tid - iy * 7;
        int rv = (wy == 7) ? (iy < 4 ? 1 : 2) : 0;
        int rh = (wx == 7) ? (ix < 4 ? 1 : 2) : 0;
        scnt[tid] = rv * 3 + rh;
    }

    // ---- load shifted window (roll(-3,-3) folded into the gather) ----
    for (int idx = tid; idx < 49 * 96; idx += BT) {
        int c = idx / 49, p = idx - c * 49;
        int iy = p / 7, ix = p - iy * 7;
        int hs = wy * 7 + iy + SH; if (hs >= HW) hs -= HW;
        int ws = wx * 7 + ix + SH; if (ws >= HW) ws -= HW;
        sm[XW + p * 100 + c] = __ldg(xb + (c * HW + hs) * HW + ws);
    }
    __syncthreads();

    // ---- LayerNorm over C=96 per position (one warp handles a position) ----
    for (int p = wrp; p < 49; p += 8) {
        float v0 = sm[XW + p*100 + lane];
        float v1 = sm[XW + p*100 + lane + 32];
        float v2 = sm[XW + p*100 + lane + 64];
        float s = v0 + v1 + v2;
        #pragma unroll
        for (int o = 16; o; o >>= 1) s += __shfl_xor_sync(0xffffffffu, s, o);
        float mu = s * (1.f / 96.f);
        float d0 = v0 - mu, d1 = v1 - mu, d2 = v2 - mu;
        float vv = d0*d0 + d1*d1 + d2*d2;
        #pragma unroll
        for (int o = 16; o; o >>= 1) vv += __shfl_xor_sync(0xffffffffu, vv, o);
        float rstd = rsqrtf(vv * (1.f / 96.f) + 1e-5f);
        sm[XW + p*100 + lane]      = d0 * rstd * __ldg(ln_g + lane)      + __ldg(ln_b + lane);
        sm[XW + p*100 + lane + 32] = d1 * rstd * __ldg(ln_g + lane + 32) + __ldg(ln_b + lane + 32);
        sm[XW + p*100 + lane + 64] = d2 * rstd * __ldg(ln_g + lane + 64) + __ldg(ln_b + lane + 64);
    }
    __syncthreads();

    const float qscale = 0.17677669529663687f;  // 32^-0.5

    // ---- QKV GEMM: (49x96) @ (96x96)^T per chunk, chunk = Q, K, V ----
    for (int ch = 0; ch < 3; ++ch) {
        // stage transposed weight tile: wT[k][oc]
        for (int idx = tid; idx < 96 * 96; idx += BT) {
            int oc = idx / 96, k = idx - oc * 96;
            sm[WO + k * 97 + oc] = __ldg(qkv_w + (ch * 96 + oc) * 96 + k);
        }
        __syncthreads();

        float acc[7][3];
        #pragma unroll
        for (int r = 0; r < 7; ++r) { acc[r][0] = 0.f; acc[r][1] = 0.f; acc[r][2] = 0.f; }

        #pragma unroll 2
        for (int k = 0; k < 96; k += 4) {
            float4 xv[7];
            #pragma unroll
            for (int r = 0; r < 7; ++r)
                xv[r] = *(const float4*)&sm[XW + (wrp + 8*r) * 100 + k];
            #pragma unroll
            for (int kk = 0; kk < 4; ++kk) {
                const float* wr = &sm[WO + (k + kk) * 97];
                float w0 = wr[lane], w1 = wr[lane + 32], w2 = wr[lane + 64];
                #pragma unroll
                for (int r = 0; r < 7; ++r) {
                    float xs = (&xv[r].x)[kk];
                    acc[r][0] += xs * w0;
                    acc[r][1] += xs * w1;
                    acc[r][2] += xs * w2;
                }
            }
        }

        #pragma unroll
        for (int r = 0; r < 7; ++r) {
            int i = wrp + 8 * r;
            if (i < 49) {
                #pragma unroll
                for (int cc = 0; cc < 3; ++cc) {
                    int c = lane + 32 * cc;
                    float val = acc[r][cc] + __ldg(qkv_b + ch * 96 + c);
                    if (ch == 0)      sm[QO + i * 100 + c] = val * qscale;
                    else if (ch == 1) sm[KO + c * 51 + i]  = val;   // K transposed
                    else              sm[VO + i * 100 + c] = val;
                }
            }
        }
        __syncthreads();
    }

    // ---- attention per head ----
    for (int h = 0; h < 3; ++h) {
        const int hb = h * 32;

        // S = Qh @ Kh^T : each thread does rows wrp+8r, cols lane & lane+32
        float acc0[7], acc1[7];
        #pragma unroll
        for (int r = 0; r < 7; ++r) { acc0[r] = 0.f; acc1[r] = 0.f; }
        const int j2 = (lane + 32 < 49) ? lane + 32 : 48;

        #pragma unroll 4
        for (int d = 0; d < 32; ++d) {
            const float* kr = &sm[KO + (hb + d) * 51];
            float k0 = kr[lane], k1 = kr[j2];
            #pragma unroll
            for (int r = 0; r < 7; ++r) {
                float qv = sm[QO + (wrp + 8*r) * 100 + hb + d];
                acc0[r] += qv * k0;
                acc1[r] += qv * k1;
            }
        }

        // add relative-position bias + shift mask, store S
        #pragma unroll
        for (int r = 0; r < 7; ++r) {
            int i = wrp + 8 * r;
            if (i < 49) {
                int yi = i / 7, xi = i - yi * 7, ci = scnt[i];
                {
                    int j = lane;
                    int yj = j / 7, xj = j - yj * 7;
                    int ridx = (yi - yj + 6) * 13 + (xi - xj + 6);
                    float bias = __ldg(rel_table + ridx * 3 + h);
                    float msk  = (scnt[j] != ci) ? -100.f : 0.f;
                    sm[SO + i * 56 + j] = acc0[r] + bias + msk;
                }
                if (lane < 17) {
                    int j = lane + 32;
                    int yj = j / 7, xj = j - yj * 7;
                    int ridx = (yi - yj + 6) * 13 + (xi - xj + 6);
                    float bias = __ldg(rel_table + ridx * 3 + h);
                    float msk  = (scnt[j] != ci) ? -100.f : 0.f;
                    sm[SO + i * 56 + j] = acc1[r] + bias + msk;
                }
            }
        }
        __syncthreads();

        // softmax over j (49), one warp per row
        for (int i = wrp; i < 49; i += 8) {
            float a0 = sm[SO + i * 56 + lane];
            float a1 = (lane < 17) ? sm[SO + i * 56 + lane + 32] : -3.0e38f;
            float mx = fmaxf(a0, a1);
            #pragma unroll
            for (int o = 16; o; o >>= 1) mx = fmaxf(mx, __shfl_xor_sync(0xffffffffu, mx, o));
            float e0 = __expf(a0 - mx);
            float e1 = (lane < 17) ? __expf(a1 - mx) : 0.f;
            float sum = e0 + e1;
            #pragma unroll
            for (int o = 16; o; o >>= 1) sum += __shfl_xor_sync(0xffffffffu, sum, o);
            float inv = 1.f / sum;
            sm[SO + i * 56 + lane] = e0 * inv;
            if (lane < 17) sm[SO + i * 56 + lane + 32] = e1 * inv;
        }
        __syncthreads();

        // out_h = S @ Vh  -> reuse XW as the attention output buffer
        float oacc[7];
        #pragma unroll
        for (int r = 0; r < 7; ++r) oacc[r] = 0.f;
        for (int j = 0; j < 49; ++j) {
            float vv = sm[VO + j * 100 + hb + lane];
            #pragma unroll
            for (int r = 0; r < 7; ++r)
                oacc[r] += sm[SO + (wrp + 8*r) * 56 + j] * vv;
        }
        #pragma unroll
        for (int r = 0; r < 7; ++r) {
            int i = wrp + 8 * r;
            if (i < 49) sm[XW + i * 100 + hb + lane] = oacc[r];
        }
        __syncthreads();
    }

    // ---- proj GEMM: (49x96) @ (96x96)^T ----
    for (int idx = tid; idx < 96 * 96; idx += BT) {
        int oc = idx / 96, k = idx - oc * 96;
        sm[WO + k * 97 + oc] = __ldg(proj_w + oc * 96 + k);
    }
    __syncthreads();

    {
        float acc[7][3];
        #pragma unroll
        for (int r = 0; r < 7; ++r) { acc[r][0] = 0.f; acc[r][1] = 0.f; acc[r][2] = 0.f; }

        #pragma unroll 2
        for (int k = 0; k < 96; k += 4) {
            float4 xv[7];
            #pragma unroll
            for (int r = 0; r < 7; ++r)
                xv[r] = *(const float4*)&sm[XW + (wrp + 8*r) * 100 + k];
            #pragma unroll
            for (int kk = 0; kk < 4; ++kk) {
                const float* wr = &sm[WO + (k + kk) * 97];
                float w0 = wr[lane], w1 = wr[lane + 32], w2 = wr[lane + 64];
                #pragma unroll
                for (int r = 0; r < 7; ++r) {
                    float xs = (&xv[r].x)[kk];
                    acc[r][0] += xs * w0;
                    acc[r][1] += xs * w1;
                    acc[r][2] += xs * w2;
                }
            }
        }

        // stage into QO (free now) for a coalesced scatter
        #pragma unroll
        for (int r = 0; r < 7; ++r) {
            int i = wrp + 8 * r;
            if (i < 49) {
                #pragma unroll
                for (int cc = 0; cc < 3; ++cc) {
                    int c = lane + 32 * cc;
                    sm[QO + i * 100 + c] = acc[r][cc] + __ldg(proj_b + c);
                }
            }
        }
    }
    __syncthreads();

    // ---- window reverse + unshift: symmetric to the load ----
    for (int idx = tid; idx < 49 * 96; idx += BT) {
        int c = idx / 49, p = idx - c * 49;
        int iy = p / 7, ix = p - iy * 7;
        int hs = wy * 7 + iy + SH; if (hs >= HW) hs -= HW;
        int ws = wx * 7 + ix + SH; if (ws >= HW) ws -= HW;
        out[((size_t)b * C + c) * (HW * HW) + hs * HW + ws] = sm[QO + p * 100 + c];
    }
}

extern "C" void kernel_launch(void* const* d_in, const int* in_sizes, int n_in,
                              void* d_out, int out_size)
{
    const float* x      = (const float*)d_in[0];
    const float* ln_g   = (const float*)d_in[1];
    const float* ln_b   = (const float*)d_in[2];
    const float* qkv_w  = (const float*)d_in[3];
    const float* qkv_b  = (const float*)d_in[4];
    const float* proj_w = (const float*)d_in[5];
    const float* proj_b = (const float*)d_in[6];
    const float* rel    = (const float*)d_in[7];
    float* out = (float*)d_out;

    const int B = in_sizes[0] / (C * HW * HW);   // 128
    const size_t smem = (size_t)SMF * sizeof(float);

    cudaFuncSetAttribute(swin_fused, cudaFuncAttributeMaxDynamicSharedMemorySize, (int)smem);
    swin_fused<<<B * 64, BT, smem>>>(x, ln_g, ln_b, qkv_w, qkv_b,
                                     proj_w, proj_b, rel, out);
}

// round 3
// speedup vs baseline: 1.6054x; 1.6054x over previous
#include <cuda_runtime.h>

namespace {
constexpr int BT = 256;   // threads per block
constexpr int C  = 96;
constexpr int HW = 56;
constexpr int SH = 3;
constexpr int RS = 96;    // row stride (floats)

// shared layout (floats)
constexpr int XW  = 0;              // LN'd input -> S scratch -> proj staging : 49 x 96
constexpr int QO  = XW + 49 * RS;   // Q (pre-scaled) -> attn output          : 49 x 96
constexpr int VO  = QO + 49 * RS;   // V                                      : 49 x 96
constexpr int KO  = VO + 49 * RS;   // K^T [c][i]                             : 96 x 49
constexpr int SMF = KO + 96 * 49;   // 18816 floats = 73.5 KiB
}

__device__ float g_wT[4 * 96 * 96];      // [ch][k][oc], ch3 = proj
__device__ float g_bias[4 * 3 * 49 * 49]; // [cls][h][i][j] : rel-pos bias + shift mask

__global__ void prep_tables(const float* __restrict__ qkv_w,
                            const float* __restrict__ proj_w,
                            const float* __restrict__ rel_table)
{
    int idx = blockIdx.x * blockDim.x + threadIdx.x;
    if (idx < 4 * 96 * 96) {
        int ch = idx / 9216, r = idx - ch * 9216;
        int k = r / 96, oc = r - k * 96;
        g_wT[idx] = (ch < 3) ? qkv_w[(ch * 96 + oc) * 96 + k]
                             : proj_w[oc * 96 + k];
    }
    if (idx < 4 * 3 * 49 * 49) {
        int t = idx;
        int j = t % 49; t /= 49;
        int i = t % 49; t /= 49;
        int h = t % 3;  int cls = t / 3;
        int yi = i / 7, xi = i - yi * 7, yj = j / 7, xj = j - yj * 7;
        float bias = rel_table[((yi - yj + 6) * 13 + (xi - xj + 6)) * 3 + h];
        int ri = ((cls & 2) ? (yi < 4 ? 1 : 2) : 0) * 3 + ((cls & 1) ? (xi < 4 ? 1 : 2) : 0);
        int rj = ((cls & 2) ? (yj < 4 ? 1 : 2) : 0) * 3 + ((cls & 1) ? (xj < 4 ? 1 : 2) : 0);
        if (ri != rj) bias -= 100.f;
        g_bias[idx] = bias;
    }
}

__global__ void __launch_bounds__(BT, 2)
swin_fused(const float* __restrict__ x,
           const float* __restrict__ ln_g, const float* __restrict__ ln_b,
           const float* __restrict__ qkv_b, const float* __restrict__ proj_b,
           float* __restrict__ out)
{
    extern __shared__ float sm[];

    const int tid  = threadIdx.x;
    const int lane = tid & 31;
    const int wrp  = tid >> 5;

    const int wid = blockIdx.x;
    const int b   = wid >> 6;
    const int w64 = wid & 63;
    const int wy  = w64 >> 3;
    const int wx  = w64 & 7;
    const int cls = ((wy == 7) ? 2 : 0) | ((wx == 7) ? 1 : 0);
    const float* xb = x + (size_t)b * C * HW * HW;

    // ---- load shifted window (roll(-3,-3) folded into the gather) ----
    for (int idx = tid; idx < 49 * 96; idx += BT) {
        int c = idx / 49, p = idx - c * 49;
        int iy = p / 7, ix = p - iy * 7;
        int hs = wy * 7 + iy + SH; if (hs >= HW) hs -= HW;
        int ws = wx * 7 + ix + SH; if (ws >= HW) ws -= HW;
        sm[XW + p * RS + c] = __ldg(xb + (c * HW + hs) * HW + ws);
    }
    __syncthreads();  // sync #1

    // ---- LayerNorm: warp owns rows p == wrp (mod 8) ----
    {
        float g0 = __ldg(ln_g + lane),      b0 = __ldg(ln_b + lane);
        float g1 = __ldg(ln_g + lane + 32), b1 = __ldg(ln_b + lane + 32);
        float g2 = __ldg(ln_g + lane + 64), b2 = __ldg(ln_b + lane + 64);
        for (int p = wrp; p < 49; p += 8) {
            float v0 = sm[XW + p*RS + lane];
            float v1 = sm[XW + p*RS + lane + 32];
            float v2 = sm[XW + p*RS + lane + 64];
            float s = v0 + v1 + v2;
            #pragma unroll
            for (int o = 16; o; o >>= 1) s += __shfl_xor_sync(0xffffffffu, s, o);
            float mu = s * (1.f / 96.f);
            float d0 = v0 - mu, d1 = v1 - mu, d2 = v2 - mu;
            float vv = d0*d0 + d1*d1 + d2*d2;
            #pragma unroll
            for (int o = 16; o; o >>= 1) vv += __shfl_xor_sync(0xffffffffu, vv, o);
            float rstd = rsqrtf(vv * (1.f / 96.f) + 1e-5f);
            sm[XW + p*RS + lane]      = d0 * rstd * g0 + b0;
            sm[XW + p*RS + lane + 32] = d1 * rstd * g1 + b1;
            sm[XW + p*RS + lane + 64] = d2 * rstd * g2 + b2;
        }
    }
    __syncwarp();

    const float qscale = 0.17677669529663687f;  // 32^-0.5

    // ---- QKV GEMMs: warp computes its rows (wrp + 8r) for all 96 out-channels ----
    #pragma unroll 1
    for (int ch = 0; ch < 3; ++ch) {
        const float* wt = g_wT + ch * 9216;
        float acc[7][3];
        #pragma unroll
        for (int r = 0; r < 7; ++r) { acc[r][0] = 0.f; acc[r][1] = 0.f; acc[r][2] = 0.f; }

        #pragma unroll 2
        for (int k = 0; k < 96; k += 4) {
            float4 xv[7];
            #pragma unroll
            for (int r = 0; r < 7; ++r)
                xv[r] = *(const float4*)&sm[XW + (wrp + 8*r) * RS + k];
            #pragma unroll
            for (int kk = 0; kk < 4; ++kk) {
                const float* wr = wt + (k + kk) * 96;
                float w0 = __ldg(wr + lane);
                float w1 = __ldg(wr + lane + 32);
                float w2 = __ldg(wr + lane + 64);
                #pragma unroll
                for (int r = 0; r < 7; ++r) {
                    float xs = (&xv[r].x)[kk];
                    acc[r][0] += xs * w0;
                    acc[r][1] += xs * w1;
                    acc[r][2] += xs * w2;
                }
            }
        }

        float bb0 = __ldg(qkv_b + ch*96 + lane);
        float bb1 = __ldg(qkv_b + ch*96 + lane + 32);
        float bb2 = __ldg(qkv_b + ch*96 + lane + 64);
        #pragma unroll
        for (int r = 0; r < 7; ++r) {
            int i = wrp + 8 * r;
            if (i < 49) {
                float v0 = acc[r][0] + bb0, v1 = acc[r][1] + bb1, v2 = acc[r][2] + bb2;
                if (ch == 0) {
                    sm[QO + i*RS + lane]      = v0 * qscale;
                    sm[QO + i*RS + lane + 32] = v1 * qscale;
                    sm[QO + i*RS + lane + 64] = v2 * qscale;
                } else if (ch == 1) {
                    sm[KO + lane*49 + i]        = v0;   // K transposed [c][i]
                    sm[KO + (lane+32)*49 + i]   = v1;
                    sm[KO + (lane+64)*49 + i]   = v2;
                } else {
                    sm[VO + i*RS + lane]      = v0;
                    sm[VO + i*RS + lane + 32] = v1;
                    sm[VO + i*RS + lane + 64] = v2;
                }
            }
        }
    }
    __syncthreads();  // sync #2 : K,V visible to all warps

    // ---- attention, per head; all within-warp from here to proj ----
    #pragma unroll 1
    for (int h = 0; h < 3; ++h) {
        const int hb = h * 32;

        // S = Qh @ Kh^T : thread = (rows wrp+8r) x (cols lane, lane+32)
        float acc0[7], acc1[7];
        #pragma unroll
        for (int r = 0; r < 7; ++r) { acc0[r] = 0.f; acc1[r] = 0.f; }
        const int j2 = (lane + 32 < 49) ? lane + 32 : 48;

        #pragma unroll 2
        for (int d4 = 0; d4 < 8; ++d4) {
            float4 qv[7];
            #pragma unroll
            for (int r = 0; r < 7; ++r)
                qv[r] = *(const float4*)&sm[QO + (wrp + 8*r) * RS + hb + d4*4];
            #pragma unroll
            for (int kk = 0; kk < 4; ++kk) {
                const float* kr = &sm[KO + (hb + d4*4 + kk) * 49];
                float k0 = kr[lane], k1 = kr[j2];
                #pragma unroll
                for (int r = 0; r < 7; ++r) {
                    float qq = (&qv[r].x)[kk];
                    acc0[r] += qq * k0;
                    acc1[r] += qq * k1;
                }
            }
        }

        const float* bt = g_bias + (size_t)(cls * 3 + h) * 49 * 49;
        __syncwarp();   // WAR: XW scratch reuse across heads

        // bias + mask + softmax (warp-wide, lane = column), store S rows to XW[.,0:49)
        #pragma unroll
        for (int r = 0; r < 7; ++r) {
            int i  = wrp + 8 * r;
            int ii = (i < 49) ? i : 48;
            float s0 = acc0[r] + __ldg(bt + ii*49 + lane);
            float s1 = -3.0e38f;
            if (lane < 17) s1 = acc1[r] + __ldg(bt + ii*49 + lane + 32);
            float mx = fmaxf(s0, s1);
            #pragma unroll
            for (int o = 16; o; o >>= 1) mx = fmaxf(mx, __shfl_xor_sync(0xffffffffu, mx, o));
            float e0 = __expf(s0 - mx);
            float e1 = (lane < 17) ? __expf(s1 - mx) : 0.f;
            float sum = e0 + e1;
            #pragma unroll
            for (int o = 16; o; o >>= 1) sum += __shfl_xor_sync(0xffffffffu, sum, o);
            float inv = 1.f / sum;
            if (i < 49) {
                sm[XW + i*RS + lane] = e0 * inv;
                if (lane < 17) sm[XW + i*RS + lane + 32] = e1 * inv;
            }
        }
        __syncwarp();

        // out_h = S @ Vh  (S broadcast from own rows in XW), write to QO cols hb
        float oacc[7];
        #pragma unroll
        for (int r = 0; r < 7; ++r) oacc[r] = 0.f;
        #pragma unroll 2
        for (int j4 = 0; j4 < 12; ++j4) {
            float4 sv[7];
            #pragma unroll
            for (int r = 0; r < 7; ++r)
                sv[r] = *(const float4*)&sm[XW + (wrp + 8*r) * RS + j4*4];
            #pragma unroll
            for (int kk = 0; kk < 4; ++kk) {
                float vv = sm[VO + (j4*4 + kk) * RS + hb + lane];
                #pragma unroll
                for (int r = 0; r < 7; ++r)
                    oacc[r] += (&sv[r].x)[kk] * vv;
            }
        }
        {   // tail j = 48
            float vv = sm[VO + 48 * RS + hb + lane];
            #pragma unroll
            for (int r = 0; r < 7; ++r)
                oacc[r] += sm[XW + (wrp + 8*r) * RS + 48] * vv;
        }
        #pragma unroll
        for (int r = 0; r < 7; ++r) {
            int i = wrp + 8 * r;
            if (i < 49) sm[QO + i*RS + hb + lane] = oacc[r];
        }
        __syncwarp();
    }

    // ---- proj GEMM from QO (own rows), stage into XW ----
    {
        const float* wt = g_wT + 3 * 9216;
        float acc[7][3];
        #pragma unroll
        for (int r = 0; r < 7; ++r) { acc[r][0] = 0.f; acc[r][1] = 0.f; acc[r][2] = 0.f; }

        #pragma unroll 2
        for (int k = 0; k < 96; k += 4) {
            float4 xv[7];
            #pragma unroll
            for (int r = 0; r < 7; ++r)
                xv[r] = *(const float4*)&sm[QO + (wrp + 8*r) * RS + k];
            #pragma unroll
            for (int kk = 0; kk < 4; ++kk) {
                const float* wr = wt + (k + kk) * 96;
                float w0 = __ldg(wr + lane);
                float w1 = __ldg(wr + lane + 32);
                float w2 = __ldg(wr + lane + 64);
                #pragma unroll
                for (int r = 0; r < 7; ++r) {
                    float xs = (&xv[r].x)[kk];
                    acc[r][0] += xs * w0;
                    acc[r][1] += xs * w1;
                    acc[r][2] += xs * w2;
                }
            }
        }

        float pb0 = __ldg(proj_b + lane);
        float pb1 = __ldg(proj_b + lane + 32);
        float pb2 = __ldg(proj_b + lane + 64);
        #pragma unroll
        for (int r = 0; r < 7; ++r) {
            int i = wrp + 8 * r;
            if (i < 49) {
                sm[XW + i*RS + lane]      = acc[r][0] + pb0;
                sm[XW + i*RS + lane + 32] = acc[r][1] + pb1;
                sm[XW + i*RS + lane + 64] = acc[r][2] + pb2;
            }
        }
    }
    __syncthreads();  // sync #3

    // ---- window reverse + unshift, coalesced-ish scatter ----
    for (int idx = tid; idx < 49 * 96; idx += BT) {
        int c = idx / 49, p = idx - c * 49;
        int iy = p / 7, ix = p - iy * 7;
        int hs = wy * 7 + iy + SH; if (hs >= HW) hs -= HW;
        int ws = wx * 7 + ix + SH; if (ws >= HW) ws -= HW;
        out[((size_t)b * C + c) * (HW * HW) + hs * HW + ws] = sm[XW + p * RS + c];
    }
}

extern "C" void kernel_launch(void* const* d_in, const int* in_sizes, int n_in,
                              void* d_out, int out_size)
{
    const float* x      = (const float*)d_in[0];
    const float* ln_g   = (const float*)d_in[1];
    const float* ln_b   = (const float*)d_in[2];
    const float* qkv_w  = (const float*)d_in[3];
    const float* qkv_b  = (const float*)d_in[4];
    const float* proj_w = (const float*)d_in[5];
    const float* proj_b = (const float*)d_in[6];
    const float* rel    = (const float*)d_in[7];
    float* out = (float*)d_out;

    const int B = in_sizes[0] / (C * HW * HW);   // 128
    const size_t smem = (size_t)SMF * sizeof(float);

    prep_tables<<<144, 256>>>(qkv_w, proj_w, rel);

    cudaFuncSetAttribute(swin_fused, cudaFuncAttributeMaxDynamicSharedMemorySize, (int)smem);
    swin_fused<<<B * 64, BT, smem>>>(x, ln_g, ln_b, qkv_b, proj_b, out);
}

// round 4
// speedup vs baseline: 1.6310x; 1.0159x over previous
#include <cuda_runtime.h>

namespace {
constexpr int BT = 256;   // threads per block
constexpr int C  = 96;
constexpr int HW = 56;
constexpr int SH = 3;
constexpr int RS = 96;    // row stride (floats)

// shared layout (floats)
constexpr int XW  = 0;              // x/LN -> V (in place) -> proj staging : 49 x 96
constexpr int QO  = XW + 49 * RS;   // Q (pre-scaled) -> attn output        : 49 x 96
constexpr int KO  = QO + 49 * RS;   // K^T [c][i]                           : 96 x 49
constexpr int SMF = KO + 96 * 49;   // 14112 floats = 55.125 KiB
}

__device__ float g_wT[4 * 96 * 96];       // [ch][k][oc], ch3 = proj
__device__ float g_bias[4 * 3 * 49 * 49]; // [cls][h][i][j] : rel-pos bias + shift mask

__global__ void prep_tables(const float* __restrict__ qkv_w,
                            const float* __restrict__ proj_w,
                            const float* __restrict__ rel_table)
{
    int idx = blockIdx.x * blockDim.x + threadIdx.x;
    if (idx < 4 * 96 * 96) {
        int ch = idx / 9216, r = idx - ch * 9216;
        int k = r / 96, oc = r - k * 96;
        g_wT[idx] = (ch < 3) ? qkv_w[(ch * 96 + oc) * 96 + k]
                             : proj_w[oc * 96 + k];
    }
    if (idx < 4 * 3 * 49 * 49) {
        int t = idx;
        int j = t % 49; t /= 49;
        int i = t % 49; t /= 49;
        int h = t % 3;  int cls = t / 3;
        int yi = i / 7, xi = i - yi * 7, yj = j / 7, xj = j - yj * 7;
        float bias = rel_table[((yi - yj + 6) * 13 + (xi - xj + 6)) * 3 + h];
        int ri = ((cls & 2) ? (yi < 4 ? 1 : 2) : 0) * 3 + ((cls & 1) ? (xi < 4 ? 1 : 2) : 0);
        int rj = ((cls & 2) ? (yj < 4 ? 1 : 2) : 0) * 3 + ((cls & 1) ? (xj < 4 ? 1 : 2) : 0);
        if (ri != rj) bias -= 100.f;
        g_bias[idx] = bias;
    }
}

__global__ void __launch_bounds__(BT, 3)
swin_fused(const float* __restrict__ x,
           const float* __restrict__ ln_g, const float* __restrict__ ln_b,
           const float* __restrict__ qkv_b, const float* __restrict__ proj_b,
           float* __restrict__ out)
{
    extern __shared__ float sm[];

    const int tid  = threadIdx.x;
    const int lane = tid & 31;
    const int wrp  = tid >> 5;

    const int wid = blockIdx.x;
    const int b   = wid >> 6;
    const int w64 = wid & 63;
    const int wy  = w64 >> 3;
    const int wx  = w64 & 7;
    const int cls = ((wy == 7) ? 2 : 0) | ((wx == 7) ? 1 : 0);
    const float* xb = x + (size_t)b * C * HW * HW;

    // ---- load shifted window (roll(-3,-3) folded into the gather) ----
    for (int idx = tid; idx < 49 * 96; idx += BT) {
        int c = idx / 49, p = idx - c * 49;
        int iy = p / 7, ix = p - iy * 7;
        int hs = wy * 7 + iy + SH; if (hs >= HW) hs -= HW;
        int ws = wx * 7 + ix + SH; if (ws >= HW) ws -= HW;
        sm[XW + p * RS + c] = __ldg(xb + (c * HW + hs) * HW + ws);
    }
    __syncthreads();  // sync #1

    // ---- LayerNorm: warp owns rows p == wrp (mod 8) ----
    {
        float g0 = __ldg(ln_g + lane),      b0 = __ldg(ln_b + lane);
        float g1 = __ldg(ln_g + lane + 32), b1 = __ldg(ln_b + lane + 32);
        float g2 = __ldg(ln_g + lane + 64), b2 = __ldg(ln_b + lane + 64);
        for (int p = wrp; p < 49; p += 8) {
            float v0 = sm[XW + p*RS + lane];
            float v1 = sm[XW + p*RS + lane + 32];
            float v2 = sm[XW + p*RS + lane + 64];
            float s = v0 + v1 + v2;
            #pragma unroll
            for (int o = 16; o; o >>= 1) s += __shfl_xor_sync(0xffffffffu, s, o);
            float mu = s * (1.f / 96.f);
            float d0 = v0 - mu, d1 = v1 - mu, d2 = v2 - mu;
            float vv = d0*d0 + d1*d1 + d2*d2;
            #pragma unroll
            for (int o = 16; o; o >>= 1) vv += __shfl_xor_sync(0xffffffffu, vv, o);
            float rstd = rsqrtf(vv * (1.f / 96.f) + 1e-5f);
            sm[XW + p*RS + lane]      = d0 * rstd * g0 + b0;
            sm[XW + p*RS + lane + 32] = d1 * rstd * g1 + b1;
            sm[XW + p*RS + lane + 64] = d2 * rstd * g2 + b2;
        }
    }
    __syncwarp();

    const float qscale = 0.17677669529663687f;  // 32^-0.5

    // ---- QKV GEMMs: warp computes its rows (wrp + 8r) for all 96 out-channels.
    //      Reads only its OWN XW rows, so the V chunk may overwrite them in place.
    #pragma unroll 1
    for (int ch = 0; ch < 3; ++ch) {
        const float* wt = g_wT + ch * 9216;
        float acc[7][3];
        #pragma unroll
        for (int r = 0; r < 7; ++r) { acc[r][0] = 0.f; acc[r][1] = 0.f; acc[r][2] = 0.f; }

        #pragma unroll 1
        for (int k = 0; k < 96; k += 4) {
            float4 xv[7];
            #pragma unroll
            for (int r = 0; r < 7; ++r)
                xv[r] = *(const float4*)&sm[XW + (wrp + 8*r) * RS + k];
            #pragma unroll
            for (int kk = 0; kk < 4; ++kk) {
                const float* wr = wt + (k + kk) * 96;
                float w0 = __ldg(wr + lane);
                float w1 = __ldg(wr + lane + 32);
                float w2 = __ldg(wr + lane + 64);
                #pragma unroll
                for (int r = 0; r < 7; ++r) {
                    float xs = (&xv[r].x)[kk];
                    acc[r][0] += xs * w0;
                    acc[r][1] += xs * w1;
                    acc[r][2] += xs * w2;
                }
            }
        }

        float bb0 = __ldg(qkv_b + ch*96 + lane);
        float bb1 = __ldg(qkv_b + ch*96 + lane + 32);
        float bb2 = __ldg(qkv_b + ch*96 + lane + 64);
        #pragma unroll
        for (int r = 0; r < 7; ++r) {
            int i = wrp + 8 * r;
            if (i < 49) {
                float v0 = acc[r][0] + bb0, v1 = acc[r][1] + bb1, v2 = acc[r][2] + bb2;
                if (ch == 0) {
                    sm[QO + i*RS + lane]      = v0 * qscale;
                    sm[QO + i*RS + lane + 32] = v1 * qscale;
                    sm[QO + i*RS + lane + 64] = v2 * qscale;
                } else if (ch == 1) {
                    sm[KO + lane*49 + i]        = v0;   // K transposed [c][i]
                    sm[KO + (lane+32)*49 + i]   = v1;
                    sm[KO + (lane+64)*49 + i]   = v2;
                } else {
                    sm[XW + i*RS + lane]      = v0;     // V in place over LN'd x
                    sm[XW + i*RS + lane + 32] = v1;
                    sm[XW + i*RS + lane + 64] = v2;
                }
            }
        }
        if (ch == 2) __syncwarp();
    }
    __syncthreads();  // sync #2 : K (KO) and V (XW) visible to all warps

    // ---- attention, per head; no shared-memory S, no intra-head syncs ----
    #pragma unroll 1
    for (int h = 0; h < 3; ++h) {
        const int hb = h * 32;

        // S = Qh @ Kh^T : thread = (rows wrp+8r) x (cols lane, lane+32)
        float acc0[7], acc1[7];
        #pragma unroll
        for (int r = 0; r < 7; ++r) { acc0[r] = 0.f; acc1[r] = 0.f; }
        const int j2 = (lane + 32 < 49) ? lane + 32 : 48;

        #pragma unroll 1
        for (int d4 = 0; d4 < 8; ++d4) {
            float4 qv[7];
            #pragma unroll
            for (int r = 0; r < 7; ++r)
                qv[r] = *(const float4*)&sm[QO + (wrp + 8*r) * RS + hb + d4*4];
            #pragma unroll
            for (int kk = 0; kk < 4; ++kk) {
                const float* kr = &sm[KO + (hb + d4*4 + kk) * 49];
                float k0 = kr[lane], k1 = kr[j2];
                #pragma unroll
                for (int r = 0; r < 7; ++r) {
                    float qq = (&qv[r].x)[kk];
                    acc0[r] += qq * k0;
                    acc1[r] += qq * k1;
                }
            }
        }

        // bias + mask + softmax, entirely in registers (lane = column)
        const float* bt = g_bias + (size_t)(cls * 3 + h) * 49 * 49;
        #pragma unroll
        for (int r = 0; r < 7; ++r) {
            int i  = wrp + 8 * r;
            int ii = (i < 49) ? i : 48;
            float s0 = acc0[r] + __ldg(bt + ii*49 + lane);
            float s1 = -3.0e38f;
            if (lane < 17) s1 = acc1[r] + __ldg(bt + ii*49 + lane + 32);
            float mx = fmaxf(s0, s1);
            #pragma unroll
            for (int o = 16; o; o >>= 1) mx = fmaxf(mx, __shfl_xor_sync(0xffffffffu, mx, o));
            float e0 = __expf(s0 - mx);
            float e1 = (lane < 17) ? __expf(s1 - mx) : 0.f;
            float sum = e0 + e1;
            #pragma unroll
            for (int o = 16; o; o >>= 1) sum += __shfl_xor_sync(0xffffffffu, sum, o);
            float inv = 1.f / sum;
            acc0[r] = e0 * inv;     // probabilities stay in registers
            acc1[r] = e1 * inv;
        }

        // out_h = S @ Vh : S[i][j] broadcast from lane j via shuffle, V from XW
        float oacc[7];
        #pragma unroll
        for (int r = 0; r < 7; ++r) oacc[r] = 0.f;
        #pragma unroll 4
        for (int j = 0; j < 32; ++j) {
            float vv = sm[XW + j * RS + hb + lane];
            #pragma unroll
            for (int r = 0; r < 7; ++r)
                oacc[r] += __shfl_sync(0xffffffffu, acc0[r], j) * vv;
        }
        #pragma unroll 4
        for (int j = 32; j < 49; ++j) {
            float vv = sm[XW + j * RS + hb + lane];
            #pragma unroll
            for (int r = 0; r < 7; ++r)
                oacc[r] += __shfl_sync(0xffffffffu, acc1[r], j - 32) * vv;
        }
        #pragma unroll
        for (int r = 0; r < 7; ++r) {
            int i = wrp + 8 * r;
            if (i < 49) sm[QO + i*RS + hb + lane] = oacc[r];  // over consumed Q cols
        }
        __syncwarp();
    }
    __syncthreads();  // sync #3 : all warps done reading V (XW) and writing attn out

    // ---- proj GEMM from QO (own rows), stage into XW ----
    {
        const float* wt = g_wT + 3 * 9216;
        float acc[7][3];
        #pragma unroll
        for (int r = 0; r < 7; ++r) { acc[r][0] = 0.f; acc[r][1] = 0.f; acc[r][2] = 0.f; }

        #pragma unroll 1
        for (int k = 0; k < 96; k += 4) {
            float4 xv[7];
            #pragma unroll
            for (int r = 0; r < 7; ++r)
                xv[r] = *(const float4*)&sm[QO + (wrp + 8*r) * RS + k];
            #pragma unroll
            for (int kk = 0; kk < 4; ++kk) {
                const float* wr = wt + (k + kk) * 96;
                float w0 = __ldg(wr + lane);
                float w1 = __ldg(wr + lane + 32);
                float w2 = __ldg(wr + lane + 64);
                #pragma unroll
                for (int r = 0; r < 7; ++r) {
                    float xs = (&xv[r].x)[kk];
                    acc[r][0] += xs * w0;
                    acc[r][1] += xs * w1;
                    acc[r][2] += xs * w2;
                }
            }
        }

        float pb0 = __ldg(proj_b + lane);
        float pb1 = __ldg(proj_b + lane + 32);
        float pb2 = __ldg(proj_b + lane + 64);
        #pragma unroll
        for (int r = 0; r < 7; ++r) {
            int i = wrp + 8 * r;
            if (i < 49) {
                sm[XW + i*RS + lane]      = acc[r][0] + pb0;
                sm[XW + i*RS + lane + 32] = acc[r][1] + pb1;
                sm[XW + i*RS + lane + 64] = acc[r][2] + pb2;
            }
        }
    }
    __syncthreads();  // sync #4

    // ---- window reverse + unshift scatter ----
    for (int idx = tid; idx < 49 * 96; idx += BT) {
        int c = idx / 49, p = idx - c * 49;
        int iy = p / 7, ix = p - iy * 7;
        int hs = wy * 7 + iy + SH; if (hs >= HW) hs -= HW;
        int ws = wx * 7 + ix + SH; if (ws >= HW) ws -= HW;
        out[((size_t)b * C + c) * (HW * HW) + hs * HW + ws] = sm[XW + p * RS + c];
    }
}

extern "C" void kernel_launch(void* const* d_in, const int* in_sizes, int n_in,
                              void* d_out, int out_size)
{
    const float* x      = (const float*)d_in[0];
    const float* ln_g   = (const float*)d_in[1];
    const float* ln_b   = (const float*)d_in[2];
    const float* qkv_w  = (const float*)d_in[3];
    const float* qkv_b  = (const float*)d_in[4];
    const float* proj_w = (const float*)d_in[5];
    const float* proj_b = (const float*)d_in[6];
    const float* rel    = (const float*)d_in[7];
    float* out = (float*)d_out;

    const int B = in_sizes[0] / (C * HW * HW);   // 128
    const size_t smem = (size_t)SMF * sizeof(float);

    prep_tables<<<144, 256>>>(qkv_w, proj_w, rel);

    cudaFuncSetAttribute(swin_fused, cudaFuncAttributeMaxDynamicSharedMemorySize, (int)smem);
    swin_fused<<<B * 64, BT, smem>>>(x, ln_g, ln_b, qkv_b, proj_b, out);
}

// round 5
// speedup vs baseline: 2.1223x; 1.3013x over previous
#include <cuda_runtime.h>

namespace {
constexpr int BT = 256;   // threads per block
constexpr int C  = 96;
constexpr int HW = 56;
constexpr int SH = 3;
constexpr int RX = 100;   // row stride for XW / QO (conflict-free mma A loads)

// shared layout (floats)
constexpr int XW  = 0;              // x/LN (tf32) -> V (after sync) -> proj out : 49 x 100
constexpr int QO  = XW + 49 * RX;   // Q -> attn out (tf32)                      : 49 x 100
constexpr int KO  = QO + 49 * RX;   // K^T [c][i]                                : 96 x 49
constexpr int SMF = KO + 96 * 49;   // 14504 floats = 56.7 KiB
}

__device__ float g_wT[4 * 96 * 96];       // [ch][k][oc], tf32-rounded; ch3 = proj
__device__ float g_bias[4 * 3 * 49 * 49]; // [cls][h][i][j] : rel-pos bias + shift mask

__device__ __forceinline__ unsigned f2tf(float f) {
    unsigned u; asm("cvt.rna.tf32.f32 %0, %1;" : "=r"(u) : "f"(f)); return u;
}

__device__ __forceinline__ void mma8(float* c, unsigned a0, unsigned a1,
                                     unsigned a2, unsigned a3,
                                     unsigned b0, unsigned b1) {
    asm("mma.sync.aligned.m16n8k8.row.col.f32.tf32.tf32.f32 "
        "{%0,%1,%2,%3},{%4,%5,%6,%7},{%8,%9},{%0,%1,%2,%3};"
        : "+f"(c[0]), "+f"(c[1]), "+f"(c[2]), "+f"(c[3])
        : "r"(a0), "r"(a1), "r"(a2), "r"(a3), "r"(b0), "r"(b1));
}

__global__ void prep_tables(const float* __restrict__ qkv_w,
                            const float* __restrict__ proj_w,
                            const float* __restrict__ rel_table)
{
    int idx = blockIdx.x * blockDim.x + threadIdx.x;
    if (idx < 4 * 96 * 96) {
        int ch = idx / 9216, r = idx - ch * 9216;
        int k = r / 96, oc = r - k * 96;
        float w = (ch < 3) ? qkv_w[(ch * 96 + oc) * 96 + k] : proj_w[oc * 96 + k];
        g_wT[idx] = __uint_as_float(f2tf(w));   // pre-round weights to tf32
    }
    if (idx < 4 * 3 * 49 * 49) {
        int t = idx;
        int j = t % 49; t /= 49;
        int i = t % 49; t /= 49;
        int h = t % 3;  int cls = t / 3;
        int yi = i / 7, xi = i - yi * 7, yj = j / 7, xj = j - yj * 7;
        float bias = rel_table[((yi - yj + 6) * 13 + (xi - xj + 6)) * 3 + h];
        int ri = ((cls & 2) ? (yi < 4 ? 1 : 2) : 0) * 3 + ((cls & 1) ? (xi < 4 ? 1 : 2) : 0);
        int rj = ((cls & 2) ? (yj < 4 ? 1 : 2) : 0) * 3 + ((cls & 1) ? (xj < 4 ? 1 : 2) : 0);
        if (ri != rj) bias -= 100.f;
        g_bias[idx] = bias;
    }
}

__global__ void __launch_bounds__(BT, 3)
swin_fused(const float* __restrict__ x,
           const float* __restrict__ ln_g, const float* __restrict__ ln_b,
           const float* __restrict__ qkv_b, const float* __restrict__ proj_b,
           float* __restrict__ out)
{
    extern __shared__ float sm[];

    const int tid  = threadIdx.x;
    const int lane = tid & 31;
    const int wrp  = tid >> 5;

    const int wid = blockIdx.x;
    const int b   = wid >> 6;
    const int w64 = wid & 63;
    const int wy  = w64 >> 3;
    const int wx  = w64 & 7;
    const int cls = ((wy == 7) ? 2 : 0) | ((wx == 7) ? 1 : 0);
    const float* xb = x + (size_t)b * C * HW * HW;

    // mma tiling: warp = row-tile rt (16 rows) x col-half cb (48 cols, 6 n8 tiles)
    const int rt = wrp & 3;
    const int cb = (wrp >> 2) * 48;
    const int g  = lane >> 2;     // groupID (row within tile / col of B)
    const int tg = lane & 3;      // thread-in-group (col of A / row of B)
    const int ar0 = 16 * rt + g;  // A/C row 0 (row 1 = +8)

    // ---- load shifted window (roll(-3,-3) folded into the gather) ----
    for (int idx = tid; idx < 49 * 96; idx += BT) {
        int c = idx / 49, p = idx - c * 49;
        int iy = p / 7, ix = p - iy * 7;
        int hs = wy * 7 + iy + SH; if (hs >= HW) hs -= HW;
        int ws = wx * 7 + ix + SH; if (ws >= HW) ws -= HW;
        sm[XW + p * RX + c] = __ldg(xb + (c * HW + hs) * HW + ws);
    }
    __syncthreads();  // sync #1

    // ---- LayerNorm (warp owns rows p == wrp mod 8), writeback tf32-rounded ----
    {
        float g0 = __ldg(ln_g + lane),      b0 = __ldg(ln_b + lane);
        float g1 = __ldg(ln_g + lane + 32), b1 = __ldg(ln_b + lane + 32);
        float g2 = __ldg(ln_g + lane + 64), b2 = __ldg(ln_b + lane + 64);
        for (int p = wrp; p < 49; p += 8) {
            float v0 = sm[XW + p*RX + lane];
            float v1 = sm[XW + p*RX + lane + 32];
            float v2 = sm[XW + p*RX + lane + 64];
            float s = v0 + v1 + v2;
            #pragma unroll
            for (int o = 16; o; o >>= 1) s += __shfl_xor_sync(0xffffffffu, s, o);
            float mu = s * (1.f / 96.f);
            float d0 = v0 - mu, d1 = v1 - mu, d2 = v2 - mu;
            float vv = d0*d0 + d1*d1 + d2*d2;
            #pragma unroll
            for (int o = 16; o; o >>= 1) vv += __shfl_xor_sync(0xffffffffu, vv, o);
            float rstd = rsqrtf(vv * (1.f / 96.f) + 1e-5f);
            sm[XW + p*RX + lane]      = __uint_as_float(f2tf(d0 * rstd * g0 + b0));
            sm[XW + p*RX + lane + 32] = __uint_as_float(f2tf(d1 * rstd * g1 + b1));
            sm[XW + p*RX + lane + 64] = __uint_as_float(f2tf(d2 * rstd * g2 + b2));
        }
    }
    __syncthreads();  // sync #2 : LN'd x visible to all warps (mma reads all rows)

    const float qscale = 0.17677669529663687f;  // 32^-0.5

    // ---- QKV GEMMs via tf32 mma: out[49x96] = x[49x96] @ wT[96x96] ----
    float vacc[6][4];   // V result held across the sync

    #pragma unroll 1
    for (int ch = 0; ch < 3; ++ch) {
        const float* wt = g_wT + ch * 9216;
        float acc[6][4];
        #pragma unroll
        for (int t = 0; t < 6; ++t)
            { acc[t][0]=0.f; acc[t][1]=0.f; acc[t][2]=0.f; acc[t][3]=0.f; }

        #pragma unroll 1
        for (int k8 = 0; k8 < 12; ++k8) {
            const int k0 = k8 * 8;
            const float* ab = &sm[XW + ar0 * RX + k0 + tg];
            unsigned a0 = __float_as_uint(ab[0]);
            unsigned a1 = __float_as_uint(ab[8 * RX]);
            unsigned a2 = __float_as_uint(ab[4]);
            unsigned a3 = __float_as_uint(ab[8 * RX + 4]);
            const float* wb = wt + (k0 + tg) * 96 + cb + g;
            #pragma unroll
            for (int t = 0; t < 6; ++t) {
                unsigned b0 = __float_as_uint(__ldg(wb + 8 * t));
                unsigned b1 = __float_as_uint(__ldg(wb + 4 * 96 + 8 * t));
                mma8(acc[t], a0, a1, a2, a3, b0, b1);
            }
        }

        if (ch == 0) {          // Q: scaled, into QO
            #pragma unroll
            for (int t = 0; t < 6; ++t) {
                int c0 = cb + 8 * t + 2 * tg, c1 = c0 + 1;
                float bb0 = __ldg(qkv_b + c0), bb1 = __ldg(qkv_b + c1);
                if (ar0 < 49) {
                    sm[QO + ar0 * RX + c0] = (acc[t][0] + bb0) * qscale;
                    sm[QO + ar0 * RX + c1] = (acc[t][1] + bb1) * qscale;
                }
                if (ar0 + 8 < 49) {
                    sm[QO + (ar0+8) * RX + c0] = (acc[t][2] + bb0) * qscale;
                    sm[QO + (ar0+8) * RX + c1] = (acc[t][3] + bb1) * qscale;
                }
            }
        } else if (ch == 1) {   // K: transposed into KO
            #pragma unroll
            for (int t = 0; t < 6; ++t) {
                int c0 = cb + 8 * t + 2 * tg, c1 = c0 + 1;
                float bb0 = __ldg(qkv_b + 96 + c0), bb1 = __ldg(qkv_b + 96 + c1);
                if (ar0 < 49) {
                    sm[KO + c0 * 49 + ar0] = acc[t][0] + bb0;
                    sm[KO + c1 * 49 + ar0] = acc[t][1] + bb1;
                }
                if (ar0 + 8 < 49) {
                    sm[KO + c0 * 49 + ar0 + 8] = acc[t][2] + bb0;
                    sm[KO + c1 * 49 + ar0 + 8] = acc[t][3] + bb1;
                }
            }
        } else {                // V: hold in registers until x is dead
            #pragma unroll
            for (int t = 0; t < 6; ++t) {
                int c0 = cb + 8 * t + 2 * tg, c1 = c0 + 1;
                vacc[t][0] = acc[t][0] + __ldg(qkv_b + 192 + c0);
                vacc[t][1] = acc[t][1] + __ldg(qkv_b + 192 + c1);
                vacc[t][2] = acc[t][2] + __ldg(qkv_b + 192 + c0);
                vacc[t][3] = acc[t][3] + __ldg(qkv_b + 192 + c1);
            }
        }
    }
    __syncthreads();  // sync #3 : all warps done reading x from XW

    // V -> XW in place
    #pragma unroll
    for (int t = 0; t < 6; ++t) {
        int c0 = cb + 8 * t + 2 * tg, c1 = c0 + 1;
        if (ar0 < 49) {
            sm[XW + ar0 * RX + c0] = vacc[t][0];
            sm[XW + ar0 * RX + c1] = vacc[t][1];
        }
        if (ar0 + 8 < 49) {
            sm[XW + (ar0+8) * RX + c0] = vacc[t][2];
            sm[XW + (ar0+8) * RX + c1] = vacc[t][3];
        }
    }
    __syncthreads();  // sync #4 : Q (QO), K (KO), V (XW) visible to all warps

    // ---- attention per head (fp32, warp-local rows wrp+8r) ----
    #pragma unroll 1
    for (int h = 0; h < 3; ++h) {
        const int hb = h * 32;

        float acc0[7], acc1[7];
        #pragma unroll
        for (int r = 0; r < 7; ++r) { acc0[r] = 0.f; acc1[r] = 0.f; }
        const int j2 = (lane + 32 < 49) ? lane + 32 : 48;

        #pragma unroll 1
        for (int d4 = 0; d4 < 8; ++d4) {
            float4 qv[7];
            #pragma unroll
            for (int r = 0; r < 7; ++r)
                qv[r] = *(const float4*)&sm[QO + (wrp + 8*r) * RX + hb + d4*4];
            #pragma unroll
            for (int kk = 0; kk < 4; ++kk) {
                const float* kr = &sm[KO + (hb + d4*4 + kk) * 49];
                float k0 = kr[lane], k1 = kr[j2];
                #pragma unroll
                for (int r = 0; r < 7; ++r) {
                    float qq = (&qv[r].x)[kk];
                    acc0[r] += qq * k0;
                    acc1[r] += qq * k1;
                }
            }
        }

        // bias + mask + softmax in registers (lane = column)
        const float* bt = g_bias + (size_t)(cls * 3 + h) * 49 * 49;
        #pragma unroll
        for (int r = 0; r < 7; ++r) {
            int i  = wrp + 8 * r;
            int ii = (i < 49) ? i : 48;
            float s0 = acc0[r] + __ldg(bt + ii*49 + lane);
            float s1 = -3.0e38f;
            if (lane < 17) s1 = acc1[r] + __ldg(bt + ii*49 + lane + 32);
            float mx = fmaxf(s0, s1);
            #pragma unroll
            for (int o = 16; o; o >>= 1) mx = fmaxf(mx, __shfl_xor_sync(0xffffffffu, mx, o));
            float e0 = __expf(s0 - mx);
            float e1 = (lane < 17) ? __expf(s1 - mx) : 0.f;
            float sum = e0 + e1;
            #pragma unroll
            for (int o = 16; o; o >>= 1) sum += __shfl_xor_sync(0xffffffffu, sum, o);
            float inv = 1.f / sum;
            acc0[r] = e0 * inv;
            acc1[r] = e1 * inv;
        }

        // out_h = S @ Vh : S[i][j] broadcast via shuffle, V from XW
        float oacc[7];
        #pragma unroll
        for (int r = 0; r < 7; ++r) oacc[r] = 0.f;
        #pragma unroll 4
        for (int j = 0; j < 32; ++j) {
            float vv = sm[XW + j * RX + hb + lane];
            #pragma unroll
            for (int r = 0; r < 7; ++r)
                oacc[r] += __shfl_sync(0xffffffffu, acc0[r], j) * vv;
        }
        #pragma unroll 4
        for (int j = 32; j < 49; ++j) {
            float vv = sm[XW + j * RX + hb + lane];
            #pragma unroll
            for (int r = 0; r < 7; ++r)
                oacc[r] += __shfl_sync(0xffffffffu, acc1[r], j - 32) * vv;
        }
        #pragma unroll
        for (int r = 0; r < 7; ++r) {
            int i = wrp + 8 * r;
            if (i < 49)   // tf32-round: QO becomes the proj mma A operand
                sm[QO + i*RX + hb + lane] = __uint_as_float(f2tf(oacc[r]));
        }
        __syncwarp();
    }
    __syncthreads();  // sync #5 : attn output complete in QO

    // ---- proj GEMM via tf32 mma: reads QO, writes XW ----
    {
        const float* wt = g_wT + 3 * 9216;
        float acc[6][4];
        #pragma unroll
        for (int t = 0; t < 6; ++t)
            { acc[t][0]=0.f; acc[t][1]=0.f; acc[t][2]=0.f; acc[t][3]=0.f; }

        #pragma unroll 1
        for (int k8 = 0; k8 < 12; ++k8) {
            const int k0 = k8 * 8;
            const float* ab = &sm[QO + ar0 * RX + k0 + tg];
            unsigned a0 = __float_as_uint(ab[0]);
            unsigned a1 = __float_as_uint(ab[8 * RX]);
            unsigned a2 = __float_as_uint(ab[4]);
            unsigned a3 = __float_as_uint(ab[8 * RX + 4]);
            const float* wb = wt + (k0 + tg) * 96 + cb + g;
            #pragma unroll
            for (int t = 0; t < 6; ++t) {
                unsigned b0 = __float_as_uint(__ldg(wb + 8 * t));
                unsigned b1 = __float_as_uint(__ldg(wb + 4 * 96 + 8 * t));
                mma8(acc[t], a0, a1, a2, a3, b0, b1);
            }
        }

        #pragma unroll
        for (int t = 0; t < 6; ++t) {
            int c0 = cb + 8 * t + 2 * tg, c1 = c0 + 1;
            float bb0 = __ldg(proj_b + c0), bb1 = __ldg(proj_b + c1);
            if (ar0 < 49) {
                sm[XW + ar0 * RX + c0] = acc[t][0] + bb0;
                sm[XW + ar0 * RX + c1] = acc[t][1] + bb1;
            }
            if (ar0 + 8 < 49) {
                sm[XW + (ar0+8) * RX + c0] = acc[t][2] + bb0;
                sm[XW + (ar0+8) * RX + c1] = acc[t][3] + bb1;
            }
        }
    }
    __syncthreads();  // sync #6

    // ---- window reverse + unshift scatter ----
    for (int idx = tid; idx < 49 * 96; idx += BT) {
        int c = idx / 49, p = idx - c * 49;
        int iy = p / 7, ix = p - iy * 7;
        int hs = wy * 7 + iy + SH; if (hs >= HW) hs -= HW;
        int ws = wx * 7 + ix + SH; if (ws >= HW) ws -= HW;
        out[((size_t)b * C + c) * (HW * HW) + hs * HW + ws] = sm[XW + p * RX + c];
    }
}

extern "C" void kernel_launch(void* const* d_in, const int* in_sizes, int n_in,
                              void* d_out, int out_size)
{
    const float* x      = (const float*)d_in[0];
    const float* ln_g   = (const float*)d_in[1];
    const float* ln_b   = (const float*)d_in[2];
    const float* qkv_w  = (const float*)d_in[3];
    const float* qkv_b  = (const float*)d_in[4];
    const float* proj_w = (const float*)d_in[5];
    const float* proj_b = (const float*)d_in[6];
    const float* rel    = (const float*)d_in[7];
    float* out = (float*)d_out;

    const int B = in_sizes[0] / (C * HW * HW);   // 128
    const size_t smem = (size_t)SMF * sizeof(float);

    prep_tables<<<144, 256>>>(qkv_w, proj_w, rel);

    cudaFuncSetAttribute(swin_fused, cudaFuncAttributeMaxDynamicSharedMemorySize, (int)smem);
    swin_fused<<<B * 64, BT, smem>>>(x, ln_g, ln_b, qkv_b, proj_b, out);
}

// round 7
// speedup vs baseline: 2.8500x; 1.3429x over previous
#include <cuda_runtime.h>

namespace {
constexpr int BT = 256;   // threads per block
constexpr int C  = 96;
constexpr int HW = 56;
constexpr int SH = 3;
constexpr int RX = 100;   // row stride for XW / QO (conflict-free mma A loads)
constexpr int RSO = 52;   // S row stride (float4-aligned)

// shared layout (floats)
constexpr int XW  = 0;              // x/LN (tf32) -> V (after sync) -> proj out : 49 x 100
constexpr int QO  = XW + 49 * RX;   // Q -> attn out (tf32)                      : 49 x 100
constexpr int KO  = QO + 49 * RX;   // K^T [c][i]                                : 96 x 49
constexpr int SO  = KO + 96 * 49;   // softmax probabilities                     : 56 x 52
constexpr int SMF = SO + 56 * RSO;  // 56 rows: padding rows 49..55 are read
                                    //   (values discarded) by the S@V float4 loop.
                                    // 17416 floats = 68.0 KiB
}

// B operands pre-packed in m16n8k8 tf32 fragment order:
// index = ((((ch*2 + cbh)*12 + k8)*3 + tp)*32 + lane)*4 + q
//   q=0: B[k8*8+tg  ][cbh*48 + (2tp  )*8 + g]   (b0 of tile t=2tp)
//   q=1: B[k8*8+tg+4][cbh*48 + (2tp  )*8 + g]   (b1 of tile t=2tp)
//   q=2,3: same for tile t=2tp+1          (g=lane>>2, tg=lane&3)
__device__ float g_wB[4 * 2 * 12 * 3 * 128];   // 147 KB, tf32-rounded
__device__ float g_bias[4 * 3 * 49 * 49];      // [cls][h][i][j] : bias + shift mask

__device__ __forceinline__ unsigned f2tf(float f) {
    unsigned u; asm("cvt.rna.tf32.f32 %0, %1;" : "=r"(u) : "f"(f)); return u;
}

__device__ __forceinline__ void mma8(float* c, unsigned a0, unsigned a1,
                                     unsigned a2, unsigned a3,
                                     float b0f, float b1f) {
    asm("mma.sync.aligned.m16n8k8.row.col.f32.tf32.tf32.f32 "
        "{%0,%1,%2,%3},{%4,%5,%6,%7},{%8,%9},{%0,%1,%2,%3};"
        : "+f"(c[0]), "+f"(c[1]), "+f"(c[2]), "+f"(c[3])
        : "r"(a0), "r"(a1), "r"(a2), "r"(a3),
          "r"(__float_as_uint(b0f)), "r"(__float_as_uint(b1f)));
}

__global__ void prep_tables(const float* __restrict__ qkv_w,
                            const float* __restrict__ proj_w,
                            const float* __restrict__ rel_table)
{
    int idx = blockIdx.x * blockDim.x + threadIdx.x;
    if (idx < 4 * 2 * 12 * 3 * 128) {
        int q    = idx & 3;
        int lane = (idx >> 2) & 31;
        int tp   = (idx >> 7) % 3;
        int k8   = (idx / 384) % 12;
        int cbh  = (idx / 4608) & 1;
        int ch   = idx / 9216;
        int g = lane >> 2, tg = lane & 3;
        int k = k8 * 8 + tg + (q & 1) * 4;
        int n = cbh * 48 + (2 * tp + (q >> 1)) * 8 + g;
        float w = (ch < 3) ? qkv_w[(ch * 96 + n) * 96 + k] : proj_w[n * 96 + k];
        g_wB[idx] = __uint_as_float(f2tf(w));
    }
    if (idx < 4 * 3 * 49 * 49) {
        int t = idx;
        int j = t % 49; t /= 49;
        int i = t % 49; t /= 49;
        int h = t % 3;  int cls = t / 3;
        int yi = i / 7, xi = i - yi * 7, yj = j / 7, xj = j - yj * 7;
        float bias = rel_table[((yi - yj + 6) * 13 + (xi - xj + 6)) * 3 + h];
        int ri = ((cls & 2) ? (yi < 4 ? 1 : 2) : 0) * 3 + ((cls & 1) ? (xi < 4 ? 1 : 2) : 0);
        int rj = ((cls & 2) ? (yj < 4 ? 1 : 2) : 0) * 3 + ((cls & 1) ? (xj < 4 ? 1 : 2) : 0);
        if (ri != rj) bias -= 100.f;
        g_bias[idx] = bias;
    }
}

__global__ void __launch_bounds__(BT, 3)
swin_fused(const float* __restrict__ x,
           const float* __restrict__ ln_g, const float* __restrict__ ln_b,
           const float* __restrict__ qkv_b, const float* __restrict__ proj_b,
           float* __restrict__ out)
{
    extern __shared__ float sm[];

    const int tid  = threadIdx.x;
    const int lane = tid & 31;
    const int wrp  = tid >> 5;

    const int wid = blockIdx.x;
    const int b   = wid >> 6;
    const int w64 = wid & 63;
    const int wy  = w64 >> 3;
    const int wx  = w64 & 7;
    const int cls = ((wy == 7) ? 2 : 0) | ((wx == 7) ? 1 : 0);
    const float* xb = x + (size_t)b * C * HW * HW;

    // mma tiling: warp = row-tile rt (16 rows) x col-half cbh (48 cols, 6 n8 tiles)
    const int rt  = wrp & 3;
    const int cbh = wrp >> 2;
    const int cb  = cbh * 48;
    const int g   = lane >> 2;     // groupID
    const int tg  = lane & 3;      // thread-in-group
    const int ar0 = 16 * rt + g;   // A/C row 0 (row 1 = +8)

    // ---- load shifted window (roll(-3,-3) folded into the gather) ----
    for (int idx = tid; idx < 49 * 96; idx += BT) {
        int c = idx / 49, p = idx - c * 49;
        int iy = p / 7, ix = p - iy * 7;
        int hs = wy * 7 + iy + SH; if (hs >= HW) hs -= HW;
        int ws = wx * 7 + ix + SH; if (ws >= HW) ws -= HW;
        sm[XW + p * RX + c] = __ldg(xb + (c * HW + hs) * HW + ws);
    }
    __syncthreads();  // sync #1

    // ---- LayerNorm (warp owns rows p == wrp mod 8), writeback tf32-rounded ----
    {
        float g0 = __ldg(ln_g + lane),      b0 = __ldg(ln_b + lane);
        float g1 = __ldg(ln_g + lane + 32), b1 = __ldg(ln_b + lane + 32);
        float g2 = __ldg(ln_g + lane + 64), b2 = __ldg(ln_b + lane + 64);
        for (int p = wrp; p < 49; p += 8) {
            float v0 = sm[XW + p*RX + lane];
            float v1 = sm[XW + p*RX + lane + 32];
            float v2 = sm[XW + p*RX + lane + 64];
            float s = v0 + v1 + v2;
            #pragma unroll
            for (int o = 16; o; o >>= 1) s += __shfl_xor_sync(0xffffffffu, s, o);
            float mu = s * (1.f / 96.f);
            float d0 = v0 - mu, d1 = v1 - mu, d2 = v2 - mu;
            float vv = d0*d0 + d1*d1 + d2*d2;
            #pragma unroll
            for (int o = 16; o; o >>= 1) vv += __shfl_xor_sync(0xffffffffu, vv, o);
            float rstd = rsqrtf(vv * (1.f / 96.f) + 1e-5f);
            sm[XW + p*RX + lane]      = __uint_as_float(f2tf(d0 * rstd * g0 + b0));
            sm[XW + p*RX + lane + 32] = __uint_as_float(f2tf(d1 * rstd * g1 + b1));
            sm[XW + p*RX + lane + 64] = __uint_as_float(f2tf(d2 * rstd * g2 + b2));
        }
    }
    __syncthreads();  // sync #2 : LN'd x visible to all warps

    const float qscale = 0.17677669529663687f;  // 32^-0.5

    // ---- QKV GEMMs via tf32 mma, B from packed fragment table ----
    float vacc[6][4];   // V result held across the sync

    #pragma unroll 1
    for (int ch = 0; ch < 3; ++ch) {
        const float4* wb4 = (const float4*)g_wB + ((ch * 2 + cbh) * 36) * 32 + lane;
        float acc[6][4];
        #pragma unroll
        for (int t = 0; t < 6; ++t)
            { acc[t][0]=0.f; acc[t][1]=0.f; acc[t][2]=0.f; acc[t][3]=0.f; }

        #pragma unroll 1
        for (int k8 = 0; k8 < 12; ++k8) {
            const float* ab = &sm[XW + ar0 * RX + k8 * 8 + tg];
            unsigned a0 = __float_as_uint(ab[0]);
            unsigned a1 = __float_as_uint(ab[8 * RX]);
            unsigned a2 = __float_as_uint(ab[4]);
            unsigned a3 = __float_as_uint(ab[8 * RX + 4]);
            #pragma unroll
            for (int tp = 0; tp < 3; ++tp) {
                float4 w4 = __ldg(wb4 + (k8 * 3 + tp) * 32);
                mma8(acc[2*tp],   a0, a1, a2, a3, w4.x, w4.y);
                mma8(acc[2*tp+1], a0, a1, a2, a3, w4.z, w4.w);
            }
        }

        if (ch == 0) {          // Q: scaled, into QO
            #pragma unroll
            for (int t = 0; t < 6; ++t) {
                int c0 = cb + 8 * t + 2 * tg, c1 = c0 + 1;
                float bb0 = __ldg(qkv_b + c0), bb1 = __ldg(qkv_b + c1);
                if (ar0 < 49) {
                    sm[QO + ar0 * RX + c0] = (acc[t][0] + bb0) * qscale;
                    sm[QO + ar0 * RX + c1] = (acc[t][1] + bb1) * qscale;
                }
                if (ar0 + 8 < 49) {
                    sm[QO + (ar0+8) * RX + c0] = (acc[t][2] + bb0) * qscale;
                    sm[QO + (ar0+8) * RX + c1] = (acc[t][3] + bb1) * qscale;
                }
            }
        } else if (ch == 1) {   // K: transposed into KO
            #pragma unroll
            for (int t = 0; t < 6; ++t) {
                int c0 = cb + 8 * t + 2 * tg, c1 = c0 + 1;
                float bb0 = __ldg(qkv_b + 96 + c0), bb1 = __ldg(qkv_b + 96 + c1);
                if (ar0 < 49) {
                    sm[KO + c0 * 49 + ar0] = acc[t][0] + bb0;
                    sm[KO + c1 * 49 + ar0] = acc[t][1] + bb1;
                }
                if (ar0 + 8 < 49) {
                    sm[KO + c0 * 49 + ar0 + 8] = acc[t][2] + bb0;
                    sm[KO + c1 * 49 + ar0 + 8] = acc[t][3] + bb1;
                }
            }
        } else {                // V: hold in registers until x is dead
            #pragma unroll
            for (int t = 0; t < 6; ++t) {
                int c0 = cb + 8 * t + 2 * tg, c1 = c0 + 1;
                vacc[t][0] = acc[t][0] + __ldg(qkv_b + 192 + c0);
                vacc[t][1] = acc[t][1] + __ldg(qkv_b + 192 + c1);
                vacc[t][2] = acc[t][2] + __ldg(qkv_b + 192 + c0);
                vacc[t][3] = acc[t][3] + __ldg(qkv_b + 192 + c1);
            }
        }
    }
    __syncthreads();  // sync #3 : all warps done reading x from XW

    // V -> XW in place
    #pragma unroll
    for (int t = 0; t < 6; ++t) {
        int c0 = cb + 8 * t + 2 * tg, c1 = c0 + 1;
        if (ar0 < 49) {
            sm[XW + ar0 * RX + c0] = vacc[t][0];
            sm[XW + ar0 * RX + c1] = vacc[t][1];
        }
        if (ar0 + 8 < 49) {
            sm[XW + (ar0+8) * RX + c0] = vacc[t][2];
            sm[XW + (ar0+8) * RX + c1] = vacc[t][3];
        }
    }
    __syncthreads();  // sync #4 : Q (QO), K (KO), V (XW) visible to all warps

    // ---- attention per head (fp32, warp-local rows wrp+8r) ----
    #pragma unroll 1
    for (int h = 0; h < 3; ++h) {
        const int hb = h * 32;

        float acc0[7], acc1[7];
        #pragma unroll
        for (int r = 0; r < 7; ++r) { acc0[r] = 0.f; acc1[r] = 0.f; }
        const int j2 = (lane + 32 < 49) ? lane + 32 : 48;

        #pragma unroll 1
        for (int d4 = 0; d4 < 8; ++d4) {
            float4 qv[7];
            #pragma unroll
            for (int r = 0; r < 7; ++r)
                qv[r] = *(const float4*)&sm[QO + (wrp + 8*r) * RX + hb + d4*4];
            #pragma unroll
            for (int kk = 0; kk < 4; ++kk) {
                const float* kr = &sm[KO + (hb + d4*4 + kk) * 49];
                float k0 = kr[lane], k1 = kr[j2];
                #pragma unroll
                for (int r = 0; r < 7; ++r) {
                    float qq = (&qv[r].x)[kk];
                    acc0[r] += qq * k0;
                    acc1[r] += qq * k1;
                }
            }
        }

        // bias + mask + softmax in registers (lane = column), store probs to SO
        const float* bt = g_bias + (size_t)(cls * 3 + h) * 49 * 49;
        #pragma unroll
        for (int r = 0; r < 7; ++r) {
            int i  = wrp + 8 * r;
            int ii = (i < 49) ? i : 48;
            float s0 = acc0[r] + __ldg(bt + ii*49 + lane);
            float s1 = -3.0e38f;
            if (lane < 17) s1 = acc1[r] + __ldg(bt + ii*49 + lane + 32);
            float mx = fmaxf(s0, s1);
            #pragma unroll
            for (int o = 16; o; o >>= 1) mx = fmaxf(mx, __shfl_xor_sync(0xffffffffu, mx, o));
            float e0 = __expf(s0 - mx);
            float e1 = (lane < 17) ? __expf(s1 - mx) : 0.f;
            float sum = e0 + e1;
            #pragma unroll
            for (int o = 16; o; o >>= 1) sum += __shfl_xor_sync(0xffffffffu, sum, o);
            float inv = 1.f / sum;
            if (i < 49) {
                sm[SO + i * RSO + lane] = e0 * inv;
                if (lane < 17) sm[SO + i * RSO + lane + 32] = e1 * inv;
            }
        }
        __syncwarp();

        // out_h = S @ Vh : S rows re-read as broadcast float4, V from XW
        float oacc[7];
        #pragma unroll
        for (int r = 0; r < 7; ++r) oacc[r] = 0.f;
        #pragma unroll 2
        for (int j4 = 0; j4 < 12; ++j4) {
            float4 sv[7];
            #pragma unroll
            for (int r = 0; r < 7; ++r)
                sv[r] = *(const float4*)&sm[SO + (wrp + 8*r) * RSO + j4*4];
            #pragma unroll
            for (int kk = 0; kk < 4; ++kk) {
                float vv = sm[XW + (j4*4 + kk) * RX + hb + lane];
                #pragma unroll
                for (int r = 0; r < 7; ++r)
                    oacc[r] += (&sv[r].x)[kk] * vv;
            }
        }
        {   // tail j = 48
            float vv = sm[XW + 48 * RX + hb + lane];
            #pragma unroll
            for (int r = 0; r < 7; ++r)
                oacc[r] += sm[SO + (wrp + 8*r) * RSO + 48] * vv;
        }
        #pragma unroll
        for (int r = 0; r < 7; ++r) {
            int i = wrp + 8 * r;
            if (i < 49)   // tf32-round: QO becomes the proj mma A operand
                sm[QO + i*RX + hb + lane] = __uint_as_float(f2tf(oacc[r]));
        }
        __syncwarp();   // WAR on SO before next head
    }
    __syncthreads();  // sync #5 : attn output complete in QO

    // ---- proj GEMM via tf32 mma: reads QO, writes XW ----
    {
        const float4* wb4 = (const float4*)g_wB + ((3 * 2 + cbh) * 36) * 32 + lane;
        float acc[6][4];
        #pragma unroll
        for (int t = 0; t < 6; ++t)
            { acc[t][0]=0.f; acc[t][1]=0.f; acc[t][2]=0.f; acc[t][3]=0.f; }

        #pragma unroll 1
        for (int k8 = 0; k8 < 12; ++k8) {
            const float* ab = &sm[QO + ar0 * RX + k8 * 8 + tg];
            unsigned a0 = __float_as_uint(ab[0]);
            unsigned a1 = __float_as_uint(ab[8 * RX]);
            unsigned a2 = __float_as_uint(ab[4]);
            unsigned a3 = __float_as_uint(ab[8 * RX + 4]);
            #pragma unroll
            for (int tp = 0; tp < 3; ++tp) {
                float4 w4 = __ldg(wb4 + (k8 * 3 + tp) * 32);
                mma8(acc[2*tp],   a0, a1, a2, a3, w4.x, w4.y);
                mma8(acc[2*tp+1], a0, a1, a2, a3, w4.z, w4.w);
            }
        }

        #pragma unroll
        for (int t = 0; t < 6; ++t) {
            int c0 = cb + 8 * t + 2 * tg, c1 = c0 + 1;
            float bb0 = __ldg(proj_b + c0), bb1 = __ldg(proj_b + c1);
            if (ar0 < 49) {
                sm[XW + ar0 * RX + c0] = acc[t][0] + bb0;
                sm[XW + ar0 * RX + c1] = acc[t][1] + bb1;
            }
            if (ar0 + 8 < 49) {
                sm[XW + (ar0+8) * RX + c0] = acc[t][2] + bb0;
                sm[XW + (ar0+8) * RX + c1] = acc[t][3] + bb1;
            }
        }
    }
    __syncthreads();  // sync #6

    // ---- window reverse + unshift scatter ----
    for (int idx = tid; idx < 49 * 96; idx += BT) {
        int c = idx / 49, p = idx - c * 49;
        int iy = p / 7, ix = p - iy * 7;
        int hs = wy * 7 + iy + SH; if (hs >= HW) hs -= HW;
        int ws = wx * 7 + ix + SH; if (ws >= HW) ws -= HW;
        out[((size_t)b * C + c) * (HW * HW) + hs * HW + ws] = sm[XW + p * RX + c];
    }
}

extern "C" void kernel_launch(void* const* d_in, const int* in_sizes, int n_in,
                              void* d_out, int out_size)
{
    const float* x      = (const float*)d_in[0];
    const float* ln_g   = (const float*)d_in[1];
    const float* ln_b   = (const float*)d_in[2];
    const float* qkv_w  = (const float*)d_in[3];
    const float* qkv_b  = (const float*)d_in[4];
    const float* proj_w = (const float*)d_in[5];
    const float* proj_b = (const float*)d_in[6];
    const float* rel    = (const float*)d_in[7];
    float* out = (float*)d_out;

    const int B = in_sizes[0] / (C * HW * HW);   // 128
    const size_t smem = (size_t)SMF * sizeof(float);

    prep_tables<<<144, 256>>>(qkv_w, proj_w, rel);

    cudaFuncSetAttribute(swin_fused, cudaFuncAttributeMaxDynamicSharedMemorySize, (int)smem);
    swin_fused<<<B * 64, BT, smem>>>(x, ln_g, ln_b, qkv_b, proj_b, out);
}

// round 8
// speedup vs baseline: 3.1941x; 1.1207x over previous
#include <cuda_runtime.h>

namespace {
constexpr int BT = 256;   // threads per block
constexpr int C  = 96;
constexpr int HW = 56;
constexpr int SH = 3;
constexpr int RX = 100;   // row stride XW/QO/KN (conflict-free mma A & B loads)
constexpr int RSO = 60;   // S row stride (28g+tg -> conflict-free A loads)

// shared layout (floats). Order matters: mma fragment loads over-read padding
// rows (A rows up to 63, B rows up to 55); every such read must land inside
// the total allocation. Max read offset = KN + 55*RX + 95 = 18755 < SMF.
constexpr int XW  = 0;              // x/LN (tf32) -> V (tf32, in place) -> proj out : 49 x 100
constexpr int QO  = XW + 49 * RX;   // Q (tf32) -> attn out (tf32)                   : 49 x 100
constexpr int SO  = QO + 49 * RX;   // S -> probs (tf32, cols 49..55 zeroed)         : 56 x 60
constexpr int KN  = SO + 56 * RSO;  // K row-major (tf32)                            : 56 x 100
constexpr int SMF = KN + 56 * RX;   // 18760 floats = 73.3 KiB
}

// B operands pre-packed in m16n8k8 tf32 fragment order:
// index = ((((ch*2 + cbh)*12 + k8)*3 + tp)*32 + lane)*4 + q
__device__ float g_wB[4 * 2 * 12 * 3 * 128];   // 147 KB, tf32-rounded
__device__ float g_bias[4 * 3 * 49 * 49];      // [cls][h][i][j] : bias + shift mask

__device__ __forceinline__ unsigned f2tf(float f) {
    unsigned u; asm("cvt.rna.tf32.f32 %0, %1;" : "=r"(u) : "f"(f)); return u;
}
__device__ __forceinline__ float f2tff(float f) { return __uint_as_float(f2tf(f)); }

__device__ __forceinline__ void mma8(float* c, unsigned a0, unsigned a1,
                                     unsigned a2, unsigned a3,
                                     float b0f, float b1f) {
    asm("mma.sync.aligned.m16n8k8.row.col.f32.tf32.tf32.f32 "
        "{%0,%1,%2,%3},{%4,%5,%6,%7},{%8,%9},{%0,%1,%2,%3};"
        : "+f"(c[0]), "+f"(c[1]), "+f"(c[2]), "+f"(c[3])
        : "r"(a0), "r"(a1), "r"(a2), "r"(a3),
          "r"(__float_as_uint(b0f)), "r"(__float_as_uint(b1f)));
}

__global__ void prep_tables(const float* __restrict__ qkv_w,
                            const float* __restrict__ proj_w,
                            const float* __restrict__ rel_table)
{
    int idx = blockIdx.x * blockDim.x + threadIdx.x;
    if (idx < 4 * 2 * 12 * 3 * 128) {
        int q    = idx & 3;
        int lane = (idx >> 2) & 31;
        int tp   = (idx >> 7) % 3;
        int k8   = (idx / 384) % 12;
        int cbh  = (idx / 4608) & 1;
        int ch   = idx / 9216;
        int g = lane >> 2, tg = lane & 3;
        int k = k8 * 8 + tg + (q & 1) * 4;
        int n = cbh * 48 + (2 * tp + (q >> 1)) * 8 + g;
        float w = (ch < 3) ? qkv_w[(ch * 96 + n) * 96 + k] : proj_w[n * 96 + k];
        g_wB[idx] = f2tff(w);
    }
    if (idx < 4 * 3 * 49 * 49) {
        int t = idx;
        int j = t % 49; t /= 49;
        int i = t % 49; t /= 49;
        int h = t % 3;  int cls = t / 3;
        int yi = i / 7, xi = i - yi * 7, yj = j / 7, xj = j - yj * 7;
        float bias = rel_table[((yi - yj + 6) * 13 + (xi - xj + 6)) * 3 + h];
        int ri = ((cls & 2) ? (yi < 4 ? 1 : 2) : 0) * 3 + ((cls & 1) ? (xi < 4 ? 1 : 2) : 0);
        int rj = ((cls & 2) ? (yj < 4 ? 1 : 2) : 0) * 3 + ((cls & 1) ? (xj < 4 ? 1 : 2) : 0);
        if (ri != rj) bias -= 100.f;
        g_bias[idx] = bias;
    }
}

__global__ void __launch_bounds__(BT, 3)
swin_fused(const float* __restrict__ x,
           const float* __restrict__ ln_g, const float* __restrict__ ln_b,
           const float* __restrict__ qkv_b, const float* __restrict__ proj_b,
           float* __restrict__ out)
{
    extern __shared__ float sm[];

    const int tid  = threadIdx.x;
    const int lane = tid & 31;
    const int wrp  = tid >> 5;

    const int wid = blockIdx.x;
    const int b   = wid >> 6;
    const int w64 = wid & 63;
    const int wy  = w64 >> 3;
    const int wx  = w64 & 7;
    const int cls = ((wy == 7) ? 2 : 0) | ((wx == 7) ? 1 : 0);
    const float* xb = x + (size_t)b * C * HW * HW;

    // mma tiling: warp = row-tile rt (16 rows) x half cbh
    const int rt  = wrp & 3;
    const int cbh = wrp >> 2;
    const int cb  = cbh * 48;
    const int g   = lane >> 2;     // groupID
    const int tg  = lane & 3;      // thread-in-group
    const int ar0 = 16 * rt + g;   // A/C row 0 (row 1 = +8)

    // ---- load shifted window (roll(-3,-3) folded into the gather) ----
    for (int idx = tid; idx < 49 * 96; idx += BT) {
        int c = idx / 49, p = idx - c * 49;
        int iy = p / 7, ix = p - iy * 7;
        int hs = wy * 7 + iy + SH; if (hs >= HW) hs -= HW;
        int ws = wx * 7 + ix + SH; if (ws >= HW) ws -= HW;
        sm[XW + p * RX + c] = __ldg(xb + (c * HW + hs) * HW + ws);
    }
    __syncthreads();

    // ---- LayerNorm (warp owns rows p == wrp mod 8), writeback tf32-rounded ----
    {
        float g0 = __ldg(ln_g + lane),      b0 = __ldg(ln_b + lane);
        float g1 = __ldg(ln_g + lane + 32), b1 = __ldg(ln_b + lane + 32);
        float g2 = __ldg(ln_g + lane + 64), b2 = __ldg(ln_b + lane + 64);
        for (int p = wrp; p < 49; p += 8) {
            float v0 = sm[XW + p*RX + lane];
            float v1 = sm[XW + p*RX + lane + 32];
            float v2 = sm[XW + p*RX + lane + 64];
            float s = v0 + v1 + v2;
            #pragma unroll
            for (int o = 16; o; o >>= 1) s += __shfl_xor_sync(0xffffffffu, s, o);
            float mu = s * (1.f / 96.f);
            float d0 = v0 - mu, d1 = v1 - mu, d2 = v2 - mu;
            float vv = d0*d0 + d1*d1 + d2*d2;
            #pragma unroll
            for (int o = 16; o; o >>= 1) vv += __shfl_xor_sync(0xffffffffu, vv, o);
            float rstd = rsqrtf(vv * (1.f / 96.f) + 1e-5f);
            sm[XW + p*RX + lane]      = f2tff(d0 * rstd * g0 + b0);
            sm[XW + p*RX + lane + 32] = f2tff(d1 * rstd * g1 + b1);
            sm[XW + p*RX + lane + 64] = f2tff(d2 * rstd * g2 + b2);
        }
    }
    __syncthreads();

    const float qscale = 0.17677669529663687f;  // 32^-0.5

    // ---- QKV GEMMs via tf32 mma, B from packed fragment table ----
    float vacc[6][4];   // V result held across the sync

    #pragma unroll 1
    for (int ch = 0; ch < 3; ++ch) {
        const float4* wb4 = (const float4*)g_wB + ((ch * 2 + cbh) * 36) * 32 + lane;
        float acc[6][4];
        #pragma unroll
        for (int t = 0; t < 6; ++t)
            { acc[t][0]=0.f; acc[t][1]=0.f; acc[t][2]=0.f; acc[t][3]=0.f; }

        #pragma unroll 1
        for (int k8 = 0; k8 < 12; ++k8) {
            const float* ab = &sm[XW + ar0 * RX + k8 * 8 + tg];
            unsigned a0 = __float_as_uint(ab[0]);
            unsigned a1 = __float_as_uint(ab[8 * RX]);
            unsigned a2 = __float_as_uint(ab[4]);
            unsigned a3 = __float_as_uint(ab[8 * RX + 4]);
            #pragma unroll
            for (int tp = 0; tp < 3; ++tp) {
                float4 w4 = __ldg(wb4 + (k8 * 3 + tp) * 32);
                mma8(acc[2*tp],   a0, a1, a2, a3, w4.x, w4.y);
                mma8(acc[2*tp+1], a0, a1, a2, a3, w4.z, w4.w);
            }
        }

        if (ch == 0) {          // Q: scaled, tf32, into QO
            #pragma unroll
            for (int t = 0; t < 6; ++t) {
                int c0 = cb + 8 * t + 2 * tg, c1 = c0 + 1;
                float bb0 = __ldg(qkv_b + c0), bb1 = __ldg(qkv_b + c1);
                if (ar0 < 49) {
                    sm[QO + ar0 * RX + c0] = f2tff((acc[t][0] + bb0) * qscale);
                    sm[QO + ar0 * RX + c1] = f2tff((acc[t][1] + bb1) * qscale);
                }
                if (ar0 + 8 < 49) {
                    sm[QO + (ar0+8) * RX + c0] = f2tff((acc[t][2] + bb0) * qscale);
                    sm[QO + (ar0+8) * RX + c1] = f2tff((acc[t][3] + bb1) * qscale);
                }
            }
        } else if (ch == 1) {   // K: row-major, tf32, into KN
            #pragma unroll
            for (int t = 0; t < 6; ++t) {
                int c0 = cb + 8 * t + 2 * tg, c1 = c0 + 1;
                float bb0 = __ldg(qkv_b + 96 + c0), bb1 = __ldg(qkv_b + 96 + c1);
                if (ar0 < 49) {
                    sm[KN + ar0 * RX + c0] = f2tff(acc[t][0] + bb0);
                    sm[KN + ar0 * RX + c1] = f2tff(acc[t][1] + bb1);
                }
                if (ar0 + 8 < 49) {
                    sm[KN + (ar0+8) * RX + c0] = f2tff(acc[t][2] + bb0);
                    sm[KN + (ar0+8) * RX + c1] = f2tff(acc[t][3] + bb1);
                }
            }
        } else {                // V: hold in registers until x is dead
            #pragma unroll
            for (int t = 0; t < 6; ++t) {
                int c0 = cb + 8 * t + 2 * tg, c1 = c0 + 1;
                vacc[t][0] = acc[t][0] + __ldg(qkv_b + 192 + c0);
                vacc[t][1] = acc[t][1] + __ldg(qkv_b + 192 + c1);
                vacc[t][2] = acc[t][2] + __ldg(qkv_b + 192 + c0);
                vacc[t][3] = acc[t][3] + __ldg(qkv_b + 192 + c1);
            }
        }
    }
    __syncthreads();  // all warps done reading x from XW

    // V -> XW in place (tf32: PV mma B operand)
    #pragma unroll
    for (int t = 0; t < 6; ++t) {
        int c0 = cb + 8 * t + 2 * tg, c1 = c0 + 1;
        if (ar0 < 49) {
            sm[XW + ar0 * RX + c0] = f2tff(vacc[t][0]);
            sm[XW + ar0 * RX + c1] = f2tff(vacc[t][1]);
        }
        if (ar0 + 8 < 49) {
            sm[XW + (ar0+8) * RX + c0] = f2tff(vacc[t][2]);
            sm[XW + (ar0+8) * RX + c1] = f2tff(vacc[t][3]);
        }
    }
    __syncthreads();  // Q (QO), K (KN), V (XW) visible to all warps

    // ---- attention per head, fully on tensor cores ----
    #pragma unroll 1
    for (int h = 0; h < 3; ++h) {
        const int hb = h * 32;

        // S = Q @ K^T : M64 x N56 x K32.  Warp: rows 16rt..16rt+15,
        // n8 tiles {0..3} (cbh=0) or {4..6} (cbh=1).
        {
            unsigned a[4][4];
            #pragma unroll
            for (int k8 = 0; k8 < 4; ++k8) {
                const float* ab = &sm[QO + ar0 * RX + hb + k8 * 8 + tg];
                a[k8][0] = __float_as_uint(ab[0]);
                a[k8][1] = __float_as_uint(ab[8 * RX]);
                a[k8][2] = __float_as_uint(ab[4]);
                a[k8][3] = __float_as_uint(ab[8 * RX + 4]);
            }
            const int n8beg = cbh ? 4 : 0;
            const int n8end = cbh ? 7 : 4;
            #pragma unroll 1
            for (int n8 = n8beg; n8 < n8end; ++n8) {
                float c[4] = {0.f, 0.f, 0.f, 0.f};
                const float* kb = &sm[KN + (8 * n8 + g) * RX + hb + tg];
                #pragma unroll
                for (int k8 = 0; k8 < 4; ++k8)
                    mma8(c, a[k8][0], a[k8][1], a[k8][2], a[k8][3],
                         kb[k8 * 8], kb[k8 * 8 + 4]);
                int j0 = 8 * n8 + 2 * tg;
                if (ar0 < 49)
                    *(float2*)&sm[SO + ar0 * RSO + j0] = make_float2(c[0], c[1]);
                if (ar0 + 8 < 49)
                    *(float2*)&sm[SO + (ar0 + 8) * RSO + j0] = make_float2(c[2], c[3]);
            }
        }
        __syncthreads();  // S complete

        // softmax rows wrp+8r: bias+mask add, max, exp, norm; probs tf32;
        // cols 49..55 zeroed (padded K-dim of the PV mma must not contribute).
        {
            const float* bt = g_bias + (size_t)(cls * 3 + h) * 49 * 49;
            #pragma unroll
            for (int r = 0; r < 7; ++r) {
                int i = wrp + 8 * r;
                if (i < 49) {   // warp-uniform branch
                    float s0 = sm[SO + i * RSO + lane] + __ldg(bt + i * 49 + lane);
                    float s1 = -3.0e38f;
                    if (lane < 17)
                        s1 = sm[SO + i * RSO + 32 + lane] + __ldg(bt + i * 49 + 32 + lane);
                    float mx = fmaxf(s0, s1);
                    #pragma unroll
                    for (int o = 16; o; o >>= 1)
                        mx = fmaxf(mx, __shfl_xor_sync(0xffffffffu, mx, o));
                    float e0 = __expf(s0 - mx);
                    float e1 = (lane < 17) ? __expf(s1 - mx) : 0.f;
                    float sum = e0 + e1;
                    #pragma unroll
                    for (int o = 16; o; o >>= 1)
                        sum += __shfl_xor_sync(0xffffffffu, sum, o);
                    float inv = 1.f / sum;
                    sm[SO + i * RSO + lane] = f2tff(e0 * inv);
                    if (lane < 17)      sm[SO + i * RSO + 32 + lane] = f2tff(e1 * inv);
                    else if (lane < 24) sm[SO + i * RSO + 32 + lane] = 0.f;
                }
            }
        }
        __syncthreads();  // probs complete

        // O = P @ V : M64 x N32 x K56.  Warp: rows 16rt..16rt+15,
        // d-tiles n8 in {2cbh, 2cbh+1}.
        {
            unsigned pa[7][4];
            #pragma unroll
            for (int k8 = 0; k8 < 7; ++k8) {
                const float* pb = &sm[SO + ar0 * RSO + k8 * 8 + tg];
                pa[k8][0] = __float_as_uint(pb[0]);
                pa[k8][1] = __float_as_uint(pb[8 * RSO]);
                pa[k8][2] = __float_as_uint(pb[4]);
                pa[k8][3] = __float_as_uint(pb[8 * RSO + 4]);
            }
            #pragma unroll
            for (int nn = 0; nn < 2; ++nn) {
                const int n8 = 2 * cbh + nn;
                float c[4] = {0.f, 0.f, 0.f, 0.f};
                const float* vb = &sm[XW + tg * RX + hb + 8 * n8 + g];
                #pragma unroll
                for (int k8 = 0; k8 < 7; ++k8)
                    mma8(c, pa[k8][0], pa[k8][1], pa[k8][2], pa[k8][3],
                         vb[k8 * 8 * RX], vb[(k8 * 8 + 4) * RX]);
                int d0 = hb + 8 * n8 + 2 * tg;
                if (ar0 < 49) {
                    sm[QO + ar0 * RX + d0]     = f2tff(c[0]);
                    sm[QO + ar0 * RX + d0 + 1] = f2tff(c[1]);
                }
                if (ar0 + 8 < 49) {
                    sm[QO + (ar0+8) * RX + d0]     = f2tff(c[2]);
                    sm[QO + (ar0+8) * RX + d0 + 1] = f2tff(c[3]);
                }
            }
        }
        __syncthreads();  // PV done reading SO; next head may overwrite S
    }

    // ---- proj GEMM via tf32 mma: reads QO, writes XW ----
    {
        const float4* wb4 = (const float4*)g_wB + ((3 * 2 + cbh) * 36) * 32 + lane;
        float acc[6][4];
        #pragma unroll
        for (int t = 0; t < 6; ++t)
            { acc[t][0]=0.f; acc[t][1]=0.f; acc[t][2]=0.f; acc[t][3]=0.f; }

        #pragma unroll 1
        for (int k8 = 0; k8 < 12; ++k8) {
            const float* ab = &sm[QO + ar0 * RX + k8 * 8 + tg];
            unsigned a0 = __float_as_uint(ab[0]);
            unsigned a1 = __float_as_uint(ab[8 * RX]);
            unsigned a2 = __float_as_uint(ab[4]);
            unsigned a3 = __float_as_uint(ab[8 * RX + 4]);
            #pragma unroll
            for (int tp = 0; tp < 3; ++tp) {
                float4 w4 = __ldg(wb4 + (k8 * 3 + tp) * 32);
                mma8(acc[2*tp],   a0, a1, a2, a3, w4.x, w4.y);
                mma8(acc[2*tp+1], a0, a1, a2, a3, w4.z, w4.w);
            }
        }

        #pragma unroll
        for (int t = 0; t < 6; ++t) {
            int c0 = cb + 8 * t + 2 * tg, c1 = c0 + 1;
            float bb0 = __ldg(proj_b + c0), bb1 = __ldg(proj_b + c1);
            if (ar0 < 49) {
                sm[XW + ar0 * RX + c0] = acc[t][0] + bb0;
                sm[XW + ar0 * RX + c1] = acc[t][1] + bb1;
            }
            if (ar0 + 8 < 49) {
                sm[XW + (ar0+8) * RX + c0] = acc[t][2] + bb0;
                sm[XW + (ar0+8) * RX + c1] = acc[t][3] + bb1;
            }
        }
    }
    __syncthreads();

    // ---- window reverse + unshift scatter ----
    for (int idx = tid; idx < 49 * 96; idx += BT) {
        int c = idx / 49, p = idx - c * 49;
        int iy = p / 7, ix = p - iy * 7;
        int hs = wy * 7 + iy + SH; if (hs >= HW) hs -= HW;
        int ws = wx * 7 + ix + SH; if (ws >= HW) ws -= HW;
        out[((size_t)b * C + c) * (HW * HW) + hs * HW + ws] = sm[XW + p * RX + c];
    }
}

extern "C" void kernel_launch(void* const* d_in, const int* in_sizes, int n_in,
                              void* d_out, int out_size)
{
    const float* x      = (const float*)d_in[0];
    const float* ln_g   = (const float*)d_in[1];
    const float* ln_b   = (const float*)d_in[2];
    const float* qkv_w  = (const float*)d_in[3];
    const float* qkv_b  = (const float*)d_in[4];
    const float* proj_w = (const float*)d_in[5];
    const float* proj_b = (const float*)d_in[6];
    const float* rel    = (const float*)d_in[7];
    float* out = (float*)d_out;

    const int B = in_sizes[0] / (C * HW * HW);   // 128
    const size_t smem = (size_t)SMF * sizeof(float);

    prep_tables<<<144, 256>>>(qkv_w, proj_w, rel);

    cudaFuncSetAttribute(swin_fused, cudaFuncAttributeMaxDynamicSharedMemorySize, (int)smem);
    swin_fused<<<B * 64, BT, smem>>>(x, ln_g, ln_b, qkv_b, proj_b, out);
}

// round 10
// speedup vs baseline: 3.2822x; 1.0276x over previous
#include <cuda_runtime.h>

namespace {
constexpr int BT = 256;   // threads per block
constexpr int C  = 96;
constexpr int HW = 56;
constexpr int SH = 3;
constexpr int RX = 100;   // row stride XW/QO/KN (conflict-free mma A & B loads)
constexpr int RSO = 60;   // S row stride (28g+tg -> conflict-free A loads)

// shared layout (floats). mma fragment loads over-read padding rows (A rows
// up to 63, B rows up to 55); all such reads stay inside the allocation and
// their values are discarded (or multiplied by explicitly zeroed P columns).
constexpr int XW  = 0;              // x/LN (tf32) -> V (tf32, in place) -> proj out : 49 x 100
constexpr int QO  = XW + 49 * RX;   // Q (tf32) -> attn out (tf32)                   : 49 x 100
constexpr int SO  = QO + 49 * RX;   // S -> probs (tf32, cols 49..55 zeroed)         : 56 x 60
constexpr int KN  = SO + 56 * RSO;  // K row-major (tf32)                            : 56 x 100
constexpr int SMF = KN + 56 * RX;   // 18760 floats = 73.3 KiB
}

// pair barrier: the two warps sharing rt (cbh = 0,1), 64 threads, id 1+rt
#define PAIRBAR() asm volatile("bar.sync %0, %1;" :: "r"(rt + 1), "r"(64) : "memory")

// B operands pre-packed in m16n8k8 tf32 fragment order:
// index = ((((ch*2 + cbh)*12 + k8)*3 + tp)*32 + lane)*4 + q
__device__ float g_wB[4 * 2 * 12 * 3 * 128];   // 147 KB, tf32-rounded
__device__ float g_bias[4 * 3 * 49 * 49];      // [cls][h][i][j] : bias + shift mask

__device__ __forceinline__ unsigned f2tf(float f) {
    unsigned u; asm("cvt.rna.tf32.f32 %0, %1;" : "=r"(u) : "f"(f)); return u;
}
__device__ __forceinline__ float f2tff(float f) { return __uint_as_float(f2tf(f)); }

__device__ __forceinline__ void mma8(float* c, unsigned a0, unsigned a1,
                                     unsigned a2, unsigned a3,
                                     float b0f, float b1f) {
    asm("mma.sync.aligned.m16n8k8.row.col.f32.tf32.tf32.f32 "
        "{%0,%1,%2,%3},{%4,%5,%6,%7},{%8,%9},{%0,%1,%2,%3};"
        : "+f"(c[0]), "+f"(c[1]), "+f"(c[2]), "+f"(c[3])
        : "r"(a0), "r"(a1), "r"(a2), "r"(a3),
          "r"(__float_as_uint(b0f)), "r"(__float_as_uint(b1f)));
}

__global__ void prep_tables(const float* __restrict__ qkv_w,
                            const float* __restrict__ proj_w,
                            const float* __restrict__ rel_table)
{
    int idx = blockIdx.x * blockDim.x + threadIdx.x;
    if (idx < 4 * 2 * 12 * 3 * 128) {
        int q    = idx & 3;
        int lane = (idx >> 2) & 31;
        int tp   = (idx >> 7) % 3;
        int k8   = (idx / 384) % 12;
        int cbh  = (idx / 4608) & 1;
        int ch   = idx / 9216;
        int g = lane >> 2, tg = lane & 3;
        int k = k8 * 8 + tg + (q & 1) * 4;
        int n = cbh * 48 + (2 * tp + (q >> 1)) * 8 + g;
        float w = (ch < 3) ? qkv_w[(ch * 96 + n) * 96 + k] : proj_w[n * 96 + k];
        g_wB[idx] = f2tff(w);
    }
    if (idx < 4 * 3 * 49 * 49) {
        int t = idx;
        int j = t % 49; t /= 49;
        int i = t % 49; t /= 49;
        int h = t % 3;  int cls = t / 3;
        int yi = i / 7, xi = i - yi * 7, yj = j / 7, xj = j - yj * 7;
        float bias = rel_table[((yi - yj + 6) * 13 + (xi - xj + 6)) * 3 + h];
        int ri = ((cls & 2) ? (yi < 4 ? 1 : 2) : 0) * 3 + ((cls & 1) ? (xi < 4 ? 1 : 2) : 0);
        int rj = ((cls & 2) ? (yj < 4 ? 1 : 2) : 0) * 3 + ((cls & 1) ? (xj < 4 ? 1 : 2) : 0);
        if (ri != rj) bias -= 100.f;
        g_bias[idx] = bias;
    }
}

__global__ void __launch_bounds__(BT, 3)
swin_fused(const float* __restrict__ x,
           const float* __restrict__ ln_g, const float* __restrict__ ln_b,
           const float* __restrict__ qkv_b, const float* __restrict__ proj_b,
           float* __restrict__ out)
{
    extern __shared__ float sm[];

    const int tid  = threadIdx.x;
    const int lane = tid & 31;
    const int wrp  = tid >> 5;

    const int wid = blockIdx.x;
    const int b   = wid >> 6;
    const int w64 = wid & 63;
    const int wy  = w64 >> 3;
    const int wx  = w64 & 7;
    const int cls = ((wy == 7) ? 2 : 0) | ((wx == 7) ? 1 : 0);
    const float* xb = x + (size_t)b * C * HW * HW;

    // mma tiling: warp = row-tile rt (16 rows) x half cbh.
    // The PAIR (rt, cbh=0|1) owns rows 16rt..16rt+15 end to end.
    const int rt  = wrp & 3;
    const int cbh = wrp >> 2;
    const int cb  = cbh * 48;
    const int g   = lane >> 2;     // groupID
    const int tg  = lane & 3;      // thread-in-group
    const int ar0 = 16 * rt + g;   // A/C row 0 (row 1 = +8)
    const int rbase = 16 * rt + 8 * cbh;  // this warp's 8 owned rows

    // ---- load shifted window (roll(-3,-3) folded into the gather) ----
    for (int idx = tid; idx < 49 * 96; idx += BT) {
        int c = idx / 49, p = idx - c * 49;
        int iy = p / 7, ix = p - iy * 7;
        int hs = wy * 7 + iy + SH; if (hs >= HW) hs -= HW;
        int ws = wx * 7 + ix + SH; if (ws >= HW) ws -= HW;
        sm[XW + p * RX + c] = __ldg(xb + (c * HW + hs) * HW + ws);
    }
    __syncthreads();  // BLOCK: gather complete

    // ---- LayerNorm on this warp's 8 owned rows, writeback tf32-rounded ----
    {
        float g0 = __ldg(ln_g + lane),      b0 = __ldg(ln_b + lane);
        float g1 = __ldg(ln_g + lane + 32), b1 = __ldg(ln_b + lane + 32);
        float g2 = __ldg(ln_g + lane + 64), b2 = __ldg(ln_b + lane + 64);
        #pragma unroll 1
        for (int rr = 0; rr < 8; ++rr) {
            int p = rbase + rr;
            if (p < 49) {   // warp-uniform
                float v0 = sm[XW + p*RX + lane];
                float v1 = sm[XW + p*RX + lane + 32];
                float v2 = sm[XW + p*RX + lane + 64];
                float s = v0 + v1 + v2;
                #pragma unroll
                for (int o = 16; o; o >>= 1) s += __shfl_xor_sync(0xffffffffu, s, o);
                float mu = s * (1.f / 96.f);
                float d0 = v0 - mu, d1 = v1 - mu, d2 = v2 - mu;
                float vv = d0*d0 + d1*d1 + d2*d2;
                #pragma unroll
                for (int o = 16; o; o >>= 1) vv += __shfl_xor_sync(0xffffffffu, vv, o);
                float rstd = rsqrtf(vv * (1.f / 96.f) + 1e-5f);
                sm[XW + p*RX + lane]      = f2tff(d0 * rstd * g0 + b0);
                sm[XW + p*RX + lane + 32] = f2tff(d1 * rstd * g1 + b1);
                sm[XW + p*RX + lane + 64] = f2tff(d2 * rstd * g2 + b2);
            }
        }
    }
    PAIRBAR();  // QKV mma A reads only pair rows (padding over-reads discarded)

    const float qscale = 0.17677669529663687f;  // 32^-0.5

    // ---- QKV GEMMs via tf32 mma, B from packed fragment table ----
    float vacc[6][4];   // V result held until pair's x rows are dead

    #pragma unroll 1
    for (int ch = 0; ch < 3; ++ch) {
        const float4* wb4 = (const float4*)g_wB + ((ch * 2 + cbh) * 36) * 32 + lane;
        float acc[6][4];
        #pragma unroll
        for (int t = 0; t < 6; ++t)
            { acc[t][0]=0.f; acc[t][1]=0.f; acc[t][2]=0.f; acc[t][3]=0.f; }

        #pragma unroll 1
        for (int k8 = 0; k8 < 12; ++k8) {
            const float* ab = &sm[XW + ar0 * RX + k8 * 8 + tg];
            unsigned a0 = __float_as_uint(ab[0]);
            unsigned a1 = __float_as_uint(ab[8 * RX]);
            unsigned a2 = __float_as_uint(ab[4]);
            unsigned a3 = __float_as_uint(ab[8 * RX + 4]);
            #pragma unroll
            for (int tp = 0; tp < 3; ++tp) {
                float4 w4 = __ldg(wb4 + (k8 * 3 + tp) * 32);
                mma8(acc[2*tp],   a0, a1, a2, a3, w4.x, w4.y);
                mma8(acc[2*tp+1], a0, a1, a2, a3, w4.z, w4.w);
            }
        }

        if (ch == 0) {          // Q: scaled, tf32, into QO
            #pragma unroll
            for (int t = 0; t < 6; ++t) {
                int c0 = cb + 8 * t + 2 * tg, c1 = c0 + 1;
                float bb0 = __ldg(qkv_b + c0), bb1 = __ldg(qkv_b + c1);
                if (ar0 < 49) {
                    sm[QO + ar0 * RX + c0] = f2tff((acc[t][0] + bb0) * qscale);
                    sm[QO + ar0 * RX + c1] = f2tff((acc[t][1] + bb1) * qscale);
                }
                if (ar0 + 8 < 49) {
                    sm[QO + (ar0+8) * RX + c0] = f2tff((acc[t][2] + bb0) * qscale);
                    sm[QO + (ar0+8) * RX + c1] = f2tff((acc[t][3] + bb1) * qscale);
                }
            }
        } else if (ch == 1) {   // K: row-major, tf32, into KN
            #pragma unroll
            for (int t = 0; t < 6; ++t) {
                int c0 = cb + 8 * t + 2 * tg, c1 = c0 + 1;
                float bb0 = __ldg(qkv_b + 96 + c0), bb1 = __ldg(qkv_b + 96 + c1);
                if (ar0 < 49) {
                    sm[KN + ar0 * RX + c0] = f2tff(acc[t][0] + bb0);
                    sm[KN + ar0 * RX + c1] = f2tff(acc[t][1] + bb1);
                }
                if (ar0 + 8 < 49) {
                    sm[KN + (ar0+8) * RX + c0] = f2tff(acc[t][2] + bb0);
                    sm[KN + (ar0+8) * RX + c1] = f2tff(acc[t][3] + bb1);
                }
            }
        } else {                // V: hold in registers
            #pragma unroll
            for (int t = 0; t < 6; ++t) {
                int c0 = cb + 8 * t + 2 * tg, c1 = c0 + 1;
                vacc[t][0] = acc[t][0] + __ldg(qkv_b + 192 + c0);
                vacc[t][1] = acc[t][1] + __ldg(qkv_b + 192 + c1);
                vacc[t][2] = acc[t][2] + __ldg(qkv_b + 192 + c0);
                vacc[t][3] = acc[t][3] + __ldg(qkv_b + 192 + c1);
            }
        }
    }
    PAIRBAR();  // pair done reading its x rows; V writes target pair rows only

    // V -> XW in place (tf32: PV mma B operand)
    #pragma unroll
    for (int t = 0; t < 6; ++t) {
        int c0 = cb + 8 * t + 2 * tg, c1 = c0 + 1;
        if (ar0 < 49) {
            sm[XW + ar0 * RX + c0] = f2tff(vacc[t][0]);
            sm[XW + ar0 * RX + c1] = f2tff(vacc[t][1]);
        }
        if (ar0 + 8 < 49) {
            sm[XW + (ar0+8) * RX + c0] = f2tff(vacc[t][2]);
            sm[XW + (ar0+8) * RX + c1] = f2tff(vacc[t][3]);
        }
    }
    __syncthreads();  // BLOCK: Q, K, V published (S/PV B-operands cross pairs)

    // ---- attention per head: pair-local pipeline, pair barriers only ----
    #pragma unroll 1
    for (int h = 0; h < 3; ++h) {
        const int hb = h * 32;

        // S = Q @ K^T : pair rows x all 56 cols (cbh splits the n8 tiles)
        {
            unsigned a[4][4];
            #pragma unroll
            for (int k8 = 0; k8 < 4; ++k8) {
                const float* ab = &sm[QO + ar0 * RX + hb + k8 * 8 + tg];
                a[k8][0] = __float_as_uint(ab[0]);
                a[k8][1] = __float_as_uint(ab[8 * RX]);
                a[k8][2] = __float_as_uint(ab[4]);
                a[k8][3] = __float_as_uint(ab[8 * RX + 4]);
            }
            const int n8beg = cbh ? 4 : 0;
            const int n8end = cbh ? 7 : 4;
            #pragma unroll 1
            for (int n8 = n8beg; n8 < n8end; ++n8) {
                float c[4] = {0.f, 0.f, 0.f, 0.f};
                const float* kb = &sm[KN + (8 * n8 + g) * RX + hb + tg];
                #pragma unroll
                for (int k8 = 0; k8 < 4; ++k8)
                    mma8(c, a[k8][0], a[k8][1], a[k8][2], a[k8][3],
                         kb[k8 * 8], kb[k8 * 8 + 4]);
                int j0 = 8 * n8 + 2 * tg;
                if (ar0 < 49)
                    *(float2*)&sm[SO + ar0 * RSO + j0] = make_float2(c[0], c[1]);
                if (ar0 + 8 < 49)
                    *(float2*)&sm[SO + (ar0 + 8) * RSO + j0] = make_float2(c[2], c[3]);
            }
        }
        PAIRBAR();  // pair's S rows complete

        // softmax on the warp's 8 owned rows; no max-subtraction (|logit|<~2
        // before the -100 mask; exp underflows to 0 on masked entries).
        // probs tf32; cols 49..55 zeroed (padded K-dim of PV).
        {
            const float* bt = g_bias + (size_t)(cls * 3 + h) * 49 * 49;
            #pragma unroll 1
            for (int rr = 0; rr < 8; ++rr) {
                int i = rbase + rr;
                if (i < 49) {   // warp-uniform
                    float e0 = __expf(sm[SO + i * RSO + lane] + __ldg(bt + i * 49 + lane));
                    float e1 = 0.f;
                    if (lane < 17)
                        e1 = __expf(sm[SO + i * RSO + 32 + lane] + __ldg(bt + i * 49 + 32 + lane));
                    float sum = e0 + e1;
                    #pragma unroll
                    for (int o = 16; o; o >>= 1)
                        sum += __shfl_xor_sync(0xffffffffu, sum, o);
                    float inv = 1.f / sum;
                    sm[SO + i * RSO + lane] = f2tff(e0 * inv);
                    if (lane < 17)      sm[SO + i * RSO + 32 + lane] = f2tff(e1 * inv);
                    else if (lane < 24) sm[SO + i * RSO + 32 + lane] = 0.f;
                }
            }
        }
        PAIRBAR();  // pair's prob rows complete

        // O = P @ V : A = pair's P rows, B = V (published at block sync)
        {
            unsigned pa[7][4];
            #pragma unroll
            for (int k8 = 0; k8 < 7; ++k8) {
                const float* pb = &sm[SO + ar0 * RSO + k8 * 8 + tg];
                pa[k8][0] = __float_as_uint(pb[0]);
                pa[k8][1] = __float_as_uint(pb[8 * RSO]);
                pa[k8][2] = __float_as_uint(pb[4]);
                pa[k8][3] = __float_as_uint(pb[8 * RSO + 4]);
            }
            #pragma unroll
            for (int nn = 0; nn < 2; ++nn) {
                const int n8 = 2 * cbh + nn;
                float c[4] = {0.f, 0.f, 0.f, 0.f};
                const float* vb = &sm[XW + tg * RX + hb + 8 * n8 + g];
                #pragma unroll
                for (int k8 = 0; k8 < 7; ++k8)
                    mma8(c, pa[k8][0], pa[k8][1], pa[k8][2], pa[k8][3],
                         vb[k8 * 8 * RX], vb[(k8 * 8 + 4) * RX]);
                int d0 = hb + 8 * n8 + 2 * tg;
                if (ar0 < 49) {
                    sm[QO + ar0 * RX + d0]     = f2tff(c[0]);
                    sm[QO + ar0 * RX + d0 + 1] = f2tff(c[1]);
                }
                if (ar0 + 8 < 49) {
                    sm[QO + (ar0+8) * RX + d0]     = f2tff(c[2]);
                    sm[QO + (ar0+8) * RX + d0 + 1] = f2tff(c[3]);
                }
            }
        }
        PAIRBAR();  // pair done reading SO; next head may overwrite pair's S rows
    }
    __syncthreads();  // BLOCK: attention done; proj will overwrite XW (V)

    // ---- proj GEMM via tf32 mma: reads QO pair rows, writes XW ----
    {
        const float4* wb4 = (const float4*)g_wB + ((3 * 2 + cbh) * 36) * 32 + lane;
        float acc[6][4];
        #pragma unroll
        for (int t = 0; t < 6; ++t)
            { acc[t][0]=0.f; acc[t][1]=0.f; acc[t][2]=0.f; acc[t][3]=0.f; }

        #pragma unroll 1
        for (int k8 = 0; k8 < 12; ++k8) {
            const float* ab = &sm[QO + ar0 * RX + k8 * 8 + tg];
            unsigned a0 = __float_as_uint(ab[0]);
            unsigned a1 = __float_as_uint(ab[8 * RX]);
            unsigned a2 = __float_as_uint(ab[4]);
            unsigned a3 = __float_as_uint(ab[8 * RX + 4]);
            #pragma unroll
            for (int tp = 0; tp < 3; ++tp) {
                float4 w4 = __ldg(wb4 + (k8 * 3 + tp) * 32);
                mma8(acc[2*tp],   a0, a1, a2, a3, w4.x, w4.y);
                mma8(acc[2*tp+1], a0, a1, a2, a3, w4.z, w4.w);
            }
        }

        #pragma unroll
        for (int t = 0; t < 6; ++t) {
            int c0 = cb + 8 * t + 2 * tg, c1 = c0 + 1;
            float bb0 = __ldg(proj_b + c0), bb1 = __ldg(proj_b + c1);
            if (ar0 < 49) {
                sm[XW + ar0 * RX + c0] = acc[t][0] + bb0;
                sm[XW + ar0 * RX + c1] = acc[t][1] + bb1;
            }
            if (ar0 + 8 < 49) {
                sm[XW + (ar0+8) * RX + c0] = acc[t][2] + bb0;
                sm[XW + (ar0+8) * RX + c1] = acc[t][3] + bb1;
            }
        }
    }
    __syncthreads();  // BLOCK: proj staged; scatter reads all rows

    // ---- window reverse + unshift scatter ----
    for (int idx = tid; idx < 49 * 96; idx += BT) {
        int c = idx / 49, p = idx - c * 49;
        int iy = p / 7, ix = p - iy * 7;
        int hs = wy * 7 + iy + SH; if (hs >= HW) hs -= HW;
        int ws = wx * 7 + ix + SH; if (ws >= HW) ws -= HW;
        out[((size_t)b * C + c) * (HW * HW) + hs * HW + ws] = sm[XW + p * RX + c];
    }
}

extern "C" void kernel_launch(void* const* d_in, const int* in_sizes, int n_in,
                              void* d_out, int out_size)
{
    const float* x      = (const float*)d_in[0];
    const float* ln_g   = (const float*)d_in[1];
    const float* ln_b   = (const float*)d_in[2];
    const float* qkv_w  = (const float*)d_in[3];
    const float* qkv_b  = (const float*)d_in[4];
    const float* proj_w = (const float*)d_in[5];
    const float* proj_b = (const float*)d_in[6];
    const float* rel    = (const float*)d_in[7];
    float* out = (float*)d_out;

    const int B = in_sizes[0] / (C * HW * HW);   // 128
    const size_t smem = (size_t)SMF * sizeof(float);

    prep_tables<<<144, 256>>>(qkv_w, proj_w, rel);

    cudaFuncSetAttribute(swin_fused, cudaFuncAttributeMaxDynamicSharedMemorySize, (int)smem);
    swin_fused<<<B * 64, BT, smem>>>(x, ln_g, ln_b, qkv_b, proj_b, out);
}

// round 12
// speedup vs baseline: 3.7887x; 1.1543x over previous
#include <cuda_runtime.h>

namespace {
constexpr int BT = 256;   // threads per block
constexpr int C  = 96;
constexpr int HW = 56;
constexpr int SH = 3;
constexpr int RX = 100;   // row stride XW/QO/KN (conflict-free mma A & B loads)
constexpr int RSO = 60;   // S row stride (28g+tg -> conflict-free A loads)

// shared layout (floats). mma fragment loads over-read padding rows (A rows
// up to 63, B rows up to 55); all such reads stay inside the allocation and
// their values are discarded (or multiplied by explicitly zeroed P columns).
constexpr int XW  = 0;              // x/LN (tf32) -> V (tf32, in place) -> proj out : 49 x 100
constexpr int QO  = XW + 49 * RX;   // Q (tf32) -> attn out (tf32)                   : 49 x 100
constexpr int SO  = QO + 49 * RX;   // S -> probs (tf32, cols 49..55 zeroed)         : 56 x 60
constexpr int KN  = SO + 56 * RSO;  // K row-major (tf32)                            : 56 x 100
constexpr int SMF = KN + 56 * RX;   // 18760 floats = 73.3 KiB
}

// pair barrier: the two warps sharing rt (cbh = 0,1), 64 threads, id 1+rt
#define PAIRBAR() asm volatile("bar.sync %0, %1;" :: "r"(rt + 1), "r"(64) : "memory")

// B operands pre-packed in m16n8k8 tf32 fragment order:
// index = ((((ch*2 + cbh)*12 + k8)*3 + tp)*32 + lane)*4 + q
__device__ float g_wB[4 * 2 * 12 * 3 * 128];   // 147 KB, tf32-rounded
__device__ float g_bias[4 * 3 * 49 * 49];      // [cls][h][i][j] : bias + shift mask

__device__ __forceinline__ unsigned f2tf(float f) {
    unsigned u; asm("cvt.rna.tf32.f32 %0, %1;" : "=r"(u) : "f"(f)); return u;
}
__device__ __forceinline__ float f2tff(float f) { return __uint_as_float(f2tf(f)); }

__device__ __forceinline__ void mma8(float* c, unsigned a0, unsigned a1,
                                     unsigned a2, unsigned a3,
                                     float b0f, float b1f) {
    asm("mma.sync.aligned.m16n8k8.row.col.f32.tf32.tf32.f32 "
        "{%0,%1,%2,%3},{%4,%5,%6,%7},{%8,%9},{%0,%1,%2,%3};"
        : "+f"(c[0]), "+f"(c[1]), "+f"(c[2]), "+f"(c[3])
        : "r"(a0), "r"(a1), "r"(a2), "r"(a3),
          "r"(__float_as_uint(b0f)), "r"(__float_as_uint(b1f)));
}

__global__ void prep_tables(const float* __restrict__ qkv_w,
                            const float* __restrict__ proj_w,
                            const float* __restrict__ rel_table)
{
    int idx = blockIdx.x * blockDim.x + threadIdx.x;
    if (idx < 4 * 2 * 12 * 3 * 128) {
        int q    = idx & 3;
        int lane = (idx >> 2) & 31;
        int tp   = (idx >> 7) % 3;
        int k8   = (idx / 384) % 12;
        int cbh  = (idx / 4608) & 1;
        int ch   = idx / 9216;
        int g = lane >> 2, tg = lane & 3;
        int k = k8 * 8 + tg + (q & 1) * 4;
        int n = cbh * 48 + (2 * tp + (q >> 1)) * 8 + g;
        float w = (ch < 3) ? qkv_w[(ch * 96 + n) * 96 + k] : proj_w[n * 96 + k];
        g_wB[idx] = f2tff(w);
    }
    if (idx < 4 * 3 * 49 * 49) {
        int t = idx;
        int j = t % 49; t /= 49;
        int i = t % 49; t /= 49;
        int h = t % 3;  int cls = t / 3;
        int yi = i / 7, xi = i - yi * 7, yj = j / 7, xj = j - yj * 7;
        float bias = rel_table[((yi - yj + 6) * 13 + (xi - xj + 6)) * 3 + h];
        int ri = ((cls & 2) ? (yi < 4 ? 1 : 2) : 0) * 3 + ((cls & 1) ? (xi < 4 ? 1 : 2) : 0);
        int rj = ((cls & 2) ? (yj < 4 ? 1 : 2) : 0) * 3 + ((cls & 1) ? (xj < 4 ? 1 : 2) : 0);
        if (ri != rj) bias -= 100.f;
        g_bias[idx] = bias;
    }
}

__global__ void __launch_bounds__(BT, 3)
swin_fused(const float* __restrict__ x,
           const float* __restrict__ ln_g, const float* __restrict__ ln_b,
           const float* __restrict__ qkv_b, const float* __restrict__ proj_b,
           float* __restrict__ out)
{
    extern __shared__ float sm[];

    const int tid  = threadIdx.x;
    const int lane = tid & 31;
    const int wrp  = tid >> 5;

    const int wid = blockIdx.x;
    const int b   = wid >> 6;
    const int w64 = wid & 63;
    const int wy  = w64 >> 3;
    const int wx  = w64 & 7;
    const int cls = ((wy == 7) ? 2 : 0) | ((wx == 7) ? 1 : 0);
    const float* xb = x + (size_t)b * C * HW * HW;

    // mma tiling: warp = row-tile rt (16 rows) x half cbh.
    // The PAIR (rt, cbh=0|1) owns rows 16rt..16rt+15 end to end.
    const int rt  = wrp & 3;
    const int cbh = wrp >> 2;
    const int cb  = cbh * 48;
    const int g   = lane >> 2;     // groupID
    const int tg  = lane & 3;      // thread-in-group
    const int ar0 = 16 * rt + g;   // A/C row 0 (row 1 = +8)
    const int rbase = 16 * rt + 8 * cbh;  // this warp's 8 owned rows

    // ---- per-lane window-position offsets (computed ONCE) ----
    // p0 = lane, p1 = lane+32 (may be >=49 -> masked)
    int off0, off1;
    {
        int iy0 = lane / 7,        ix0 = lane - iy0 * 7;
        int p1  = lane + 32;
        int iy1 = p1 / 7,          ix1 = p1 - iy1 * 7;
        int h0 = wy * 7 + iy0 + SH; if (h0 >= HW) h0 -= HW;
        int w0 = wx * 7 + ix0 + SH; if (w0 >= HW) w0 -= HW;
        int h1 = wy * 7 + iy1 + SH; if (h1 >= HW) h1 -= HW;
        int w1 = wx * 7 + ix1 + SH; if (w1 >= HW) w1 -= HW;
        off0 = h0 * HW + w0;
        off1 = h1 * HW + w1;
    }
    const bool p1ok = (lane + 32) < 49;

    // ---- gather: warp handles channels c = wrp + 8k (roll folded in) ----
    {
        const float* bp = xb + (size_t)wrp * (HW * HW);
        #pragma unroll
        for (int k = 0; k < 12; ++k) {
            int c = wrp + 8 * k;
            float v0 = __ldg(bp + off0);
            sm[XW + lane * RX + c] = v0;
            if (p1ok) sm[XW + (lane + 32) * RX + c] = __ldg(bp + off1);
            bp += 8 * (HW * HW);
        }
    }
    __syncthreads();  // BLOCK: gather complete

    // ---- LayerNorm on this warp's 8 owned rows, writeback tf32-rounded ----
    {
        float g0 = __ldg(ln_g + lane),      b0 = __ldg(ln_b + lane);
        float g1 = __ldg(ln_g + lane + 32), b1 = __ldg(ln_b + lane + 32);
        float g2 = __ldg(ln_g + lane + 64), b2 = __ldg(ln_b + lane + 64);
        #pragma unroll 1
        for (int rr = 0; rr < 8; ++rr) {
            int p = rbase + rr;
            if (p < 49) {   // warp-uniform
                float v0 = sm[XW + p*RX + lane];
                float v1 = sm[XW + p*RX + lane + 32];
                float v2 = sm[XW + p*RX + lane + 64];
                float s = v0 + v1 + v2;
                #pragma unroll
                for (int o = 16; o; o >>= 1) s += __shfl_xor_sync(0xffffffffu, s, o);
                float mu = s * (1.f / 96.f);
                float d0 = v0 - mu, d1 = v1 - mu, d2 = v2 - mu;
                float vv = d0*d0 + d1*d1 + d2*d2;
                #pragma unroll
                for (int o = 16; o; o >>= 1) vv += __shfl_xor_sync(0xffffffffu, vv, o);
                float rstd = rsqrtf(vv * (1.f / 96.f) + 1e-5f);
                sm[XW + p*RX + lane]      = f2tff(d0 * rstd * g0 + b0);
                sm[XW + p*RX + lane + 32] = f2tff(d1 * rstd * g1 + b1);
                sm[XW + p*RX + lane + 64] = f2tff(d2 * rstd * g2 + b2);
            }
        }
    }
    PAIRBAR();  // QKV mma A reads only pair rows (padding over-reads discarded)

    const float qscale = 0.17677669529663687f;  // 32^-0.5

    // ---- QKV GEMMs via tf32 mma, B from packed fragment table ----
    float vacc[6][4];   // V result held until pair's x rows are dead

    #pragma unroll 1
    for (int ch = 0; ch < 3; ++ch) {
        const float4* wb4 = (const float4*)g_wB + ((ch * 2 + cbh) * 36) * 32 + lane;
        float acc[6][4];
        #pragma unroll
        for (int t = 0; t < 6; ++t)
            { acc[t][0]=0.f; acc[t][1]=0.f; acc[t][2]=0.f; acc[t][3]=0.f; }

        #pragma unroll 2
        for (int k8 = 0; k8 < 12; ++k8) {
            const float* ab = &sm[XW + ar0 * RX + k8 * 8 + tg];
            unsigned a0 = __float_as_uint(ab[0]);
            unsigned a1 = __float_as_uint(ab[8 * RX]);
            unsigned a2 = __float_as_uint(ab[4]);
            unsigned a3 = __float_as_uint(ab[8 * RX + 4]);
            #pragma unroll
            for (int tp = 0; tp < 3; ++tp) {
                float4 w4 = __ldg(wb4 + (k8 * 3 + tp) * 32);
                mma8(acc[2*tp],   a0, a1, a2, a3, w4.x, w4.y);
                mma8(acc[2*tp+1], a0, a1, a2, a3, w4.z, w4.w);
            }
        }

        if (ch == 0) {          // Q: scaled, tf32, into QO
            #pragma unroll
            for (int t = 0; t < 6; ++t) {
                int c0 = cb + 8 * t + 2 * tg;
                float2 bb = __ldg((const float2*)(qkv_b + c0));
                if (ar0 < 49)
                    *(float2*)&sm[QO + ar0 * RX + c0] = make_float2(
                        f2tff((acc[t][0] + bb.x) * qscale),
                        f2tff((acc[t][1] + bb.y) * qscale));
                if (ar0 + 8 < 49)
                    *(float2*)&sm[QO + (ar0+8) * RX + c0] = make_float2(
                        f2tff((acc[t][2] + bb.x) * qscale),
                        f2tff((acc[t][3] + bb.y) * qscale));
            }
        } else if (ch == 1) {   // K: row-major, tf32, into KN
            #pragma unroll
            for (int t = 0; t < 6; ++t) {
                int c0 = cb + 8 * t + 2 * tg;
                float2 bb = __ldg((const float2*)(qkv_b + 96 + c0));
                if (ar0 < 49)
                    *(float2*)&sm[KN + ar0 * RX + c0] = make_float2(
                        f2tff(acc[t][0] + bb.x), f2tff(acc[t][1] + bb.y));
                if (ar0 + 8 < 49)
                    *(float2*)&sm[KN + (ar0+8) * RX + c0] = make_float2(
                        f2tff(acc[t][2] + bb.x), f2tff(acc[t][3] + bb.y));
            }
        } else {                // V: hold in registers
            #pragma unroll
            for (int t = 0; t < 6; ++t) {
                int c0 = cb + 8 * t + 2 * tg;
                float2 bb = __ldg((const float2*)(qkv_b + 192 + c0));
                vacc[t][0] = acc[t][0] + bb.x;
                vacc[t][1] = acc[t][1] + bb.y;
                vacc[t][2] = acc[t][2] + bb.x;
                vacc[t][3] = acc[t][3] + bb.y;
            }
        }
    }
    PAIRBAR();  // pair done reading its x rows; V writes target pair rows only

    // V -> XW in place (tf32: PV mma B operand)
    #pragma unroll
    for (int t = 0; t < 6; ++t) {
        int c0 = cb + 8 * t + 2 * tg;
        if (ar0 < 49)
            *(float2*)&sm[XW + ar0 * RX + c0] =
                make_float2(f2tff(vacc[t][0]), f2tff(vacc[t][1]));
        if (ar0 + 8 < 49)
            *(float2*)&sm[XW + (ar0+8) * RX + c0] =
                make_float2(f2tff(vacc[t][2]), f2tff(vacc[t][3]));
    }
    __syncthreads();  // BLOCK: Q, K, V published (S/PV B-operands cross pairs)

    // ---- attention per head: pair-local pipeline, pair barriers only ----
    #pragma unroll 1
    for (int h = 0; h < 3; ++h) {
        const int hb = h * 32;

        // S = Q @ K^T : pair rows x all 56 cols (cbh splits the n8 tiles)
        {
            unsigned a[4][4];
            #pragma unroll
            for (int k8 = 0; k8 < 4; ++k8) {
                const float* ab = &sm[QO + ar0 * RX + hb + k8 * 8 + tg];
                a[k8][0] = __float_as_uint(ab[0]);
                a[k8][1] = __float_as_uint(ab[8 * RX]);
                a[k8][2] = __float_as_uint(ab[4]);
                a[k8][3] = __float_as_uint(ab[8 * RX + 4]);
            }
            const int n8beg = cbh ? 4 : 0;
            const int n8end = cbh ? 7 : 4;
            #pragma unroll 2
            for (int n8 = n8beg; n8 < n8end; ++n8) {
                float c[4] = {0.f, 0.f, 0.f, 0.f};
                const float* kb = &sm[KN + (8 * n8 + g) * RX + hb + tg];
                #pragma unroll
                for (int k8 = 0; k8 < 4; ++k8)
                    mma8(c, a[k8][0], a[k8][1], a[k8][2], a[k8][3],
                         kb[k8 * 8], kb[k8 * 8 + 4]);
                int j0 = 8 * n8 + 2 * tg;
                if (ar0 < 49)
                    *(float2*)&sm[SO + ar0 * RSO + j0] = make_float2(c[0], c[1]);
                if (ar0 + 8 < 49)
                    *(float2*)&sm[SO + (ar0 + 8) * RSO + j0] = make_float2(c[2], c[3]);
            }
        }
        PAIRBAR();  // pair's S rows complete

        // softmax on the warp's 8 owned rows; no max-subtraction (|logit|<~2
        // before the -100 mask; exp underflows to 0 on masked entries).
        // probs tf32; cols 49..55 zeroed (padded K-dim of PV).
        {
            const float* bt = g_bias + (size_t)(cls * 3 + h) * 49 * 49;
            #pragma unroll 1
            for (int rr = 0; rr < 8; ++rr) {
                int i = rbase + rr;
                if (i < 49) {   // warp-uniform
                    float e0 = __expf(sm[SO + i * RSO + lane] + __ldg(bt + i * 49 + lane));
                    float e1 = 0.f;
                    if (lane < 17)
                        e1 = __expf(sm[SO + i * RSO + 32 + lane] + __ldg(bt + i * 49 + 32 + lane));
                    float sum = e0 + e1;
                    #pragma unroll
                    for (int o = 16; o; o >>= 1)
                        sum += __shfl_xor_sync(0xffffffffu, sum, o);
                    float inv = 1.f / sum;
                    sm[SO + i * RSO + lane] = f2tff(e0 * inv);
                    if (lane < 17)      sm[SO + i * RSO + 32 + lane] = f2tff(e1 * inv);
                    else if (lane < 24) sm[SO + i * RSO + 32 + lane] = 0.f;
                }
            }
        }
        PAIRBAR();  // pair's prob rows complete

        // O = P @ V : A = pair's P rows, B = V (published at block sync)
        {
            unsigned pa[7][4];
            #pragma unroll
            for (int k8 = 0; k8 < 7; ++k8) {
                const float* pb = &sm[SO + ar0 * RSO + k8 * 8 + tg];
                pa[k8][0] = __float_as_uint(pb[0]);
                pa[k8][1] = __float_as_uint(pb[8 * RSO]);
                pa[k8][2] = __float_as_uint(pb[4]);
                pa[k8][3] = __float_as_uint(pb[8 * RSO + 4]);
            }
            #pragma unroll
            for (int nn = 0; nn < 2; ++nn) {
                const int n8 = 2 * cbh + nn;
                float c[4] = {0.f, 0.f, 0.f, 0.f};
                const float* vb = &sm[XW + tg * RX + hb + 8 * n8 + g];
                #pragma unroll
                for (int k8 = 0; k8 < 7; ++k8)
                    mma8(c, pa[k8][0], pa[k8][1], pa[k8][2], pa[k8][3],
                         vb[k8 * 8 * RX], vb[(k8 * 8 + 4) * RX]);
                int d0 = hb + 8 * n8 + 2 * tg;
                if (ar0 < 49)
                    *(float2*)&sm[QO + ar0 * RX + d0] =
                        make_float2(f2tff(c[0]), f2tff(c[1]));
                if (ar0 + 8 < 49)
                    *(float2*)&sm[QO + (ar0+8) * RX + d0] =
                        make_float2(f2tff(c[2]), f2tff(c[3]));
            }
        }
        PAIRBAR();  // pair done reading SO; next head may overwrite pair's S rows
    }
    __syncthreads();  // BLOCK: attention done; proj will overwrite XW (V)

    // ---- proj GEMM via tf32 mma: reads QO pair rows, writes XW ----
    {
        const float4* wb4 = (const float4*)g_wB + ((3 * 2 + cbh) * 36) * 32 + lane;
        float acc[6][4];
        #pragma unroll
        for (int t = 0; t < 6; ++t)
            { acc[t][0]=0.f; acc[t][1]=0.f; acc[t][2]=0.f; acc[t][3]=0.f; }

        #pragma unroll 2
        for (int k8 = 0; k8 < 12; ++k8) {
            const float* ab = &sm[QO + ar0 * RX + k8 * 8 + tg];
            unsigned a0 = __float_as_uint(ab[0]);
            unsigned a1 = __float_as_uint(ab[8 * RX]);
            unsigned a2 = __float_as_uint(ab[4]);
            unsigned a3 = __float_as_uint(ab[8 * RX + 4]);
            #pragma unroll
            for (int tp = 0; tp < 3; ++tp) {
                float4 w4 = __ldg(wb4 + (k8 * 3 + tp) * 32);
                mma8(acc[2*tp],   a0, a1, a2, a3, w4.x, w4.y);
                mma8(acc[2*tp+1], a0, a1, a2, a3, w4.z, w4.w);
            }
        }

        #pragma unroll
        for (int t = 0; t < 6; ++t) {
            int c0 = cb + 8 * t + 2 * tg;
            float2 bb = __ldg((const float2*)(proj_b + c0));
            if (ar0 < 49)
                *(float2*)&sm[XW + ar0 * RX + c0] =
                    make_float2(acc[t][0] + bb.x, acc[t][1] + bb.y);
            if (ar0 + 8 < 49)
                *(float2*)&sm[XW + (ar0+8) * RX + c0] =
                    make_float2(acc[t][2] + bb.x, acc[t][3] + bb.y);
        }
    }
    __syncthreads();  // BLOCK: proj staged; scatter reads all rows

    // ---- window reverse + unshift scatter (precomputed offsets) ----
    {
        float* op = out + ((size_t)b * C + wrp) * (HW * HW);
        #pragma unroll
        for (int k = 0; k < 12; ++k) {
            int c = wrp + 8 * k;
            op[off0] = sm[XW + lane * RX + c];
            if (p1ok) op[off1] = sm[XW + (lane + 32) * RX + c];
            op += 8 * (HW * HW);
        }
    }
}

extern "C" void kernel_launch(void* const* d_in, const int* in_sizes, int n_in,
                              void* d_out, int out_size)
{
    const float* x      = (const float*)d_in[0];
    const float* ln_g   = (const float*)d_in[1];
    const float* ln_b   = (const float*)d_in[2];
    const float* qkv_w  = (const float*)d_in[3];
    const float* qkv_b  = (const float*)d_in[4];
    const float* proj_w = (const float*)d_in[5];
    const float* proj_b = (const float*)d_in[6];
    const float* rel    = (const float*)d_in[7];
    float* out = (float*)d_out;

    const int B = in_sizes[0] / (C * HW * HW);   // 128
    const size_t smem = (size_t)SMF * sizeof(float);

    prep_tables<<<144, 256>>>(qkv_w, proj_w, rel);

    cudaFuncSetAttribute(swin_fused, cudaFuncAttributeMaxDynamicSharedMemorySize, (int)smem);
    swin_fused<<<B * 64, BT, smem>>>(x, ln_g, ln_b, qkv_b, proj_b, out);
}

// round 14
// speedup vs baseline: 7.2458x; 1.9125x over previous
#include <cuda_runtime.h>
#include <cuda_fp16.h>

namespace {
constexpr int BT = 256;   // threads per block
constexpr int C  = 96;
constexpr int HW = 56;
constexpr int SH = 3;

// strides in HALVES. Rule for conflict-free mma A/B loads (LDS.32 at
// half-index r*stride + 2tg): stride ≡ 8 (mod 16).
constexpr int RXh = 104;  // XW / QO / KN rows
constexpr int RSh = 72;   // SP (probs) rows
constexpr int RVh = 72;   // Vt rows

// shared layout (half indices). Over-read audit: A-fragment rows reach 63,
// B rows reach 55/95; every such access lands inside the allocation and its
// value is either discarded (M-dim) or multiplied by explicit zeros (K-dim).
constexpr int XWh = 0;                  // x/LN fp16                      : 49 x 104
constexpr int QOh = XWh + 49 * RXh;     // Q fp16 -> attn out fp16        : 49 x 104
constexpr int KNh = QOh + 49 * RXh;     // K row-major fp16               : 56 x 104
constexpr int SPh = KNh + 56 * RXh;     // probs fp16 (cols 49..63 zero)  : 49 x 72
constexpr int VTh = SPh + 49 * RSh;     // V transposed [d][j] fp16       : 96 x 72
constexpr int RSHh = VTh + 96 * RVh;    // rowsum floats (128) = 256 halves
constexpr int SMH  = RSHh + 256;        // 26712 halves = 53424 B
constexpr int RSF  = RSHh / 2;          // float index of rowsum buffer
constexpr int FSTf = KNh / 2;           // float idx of fp32 proj staging (KN..Vt dead)
}

// pair barrier: the two warps sharing rt (cbh = 0,1), 64 threads, id 1+rt
#define PAIRBAR() asm volatile("bar.sync %0, %1;" :: "r"(rt + 1), "r"(64) : "memory")

// fp16 B operands packed in m16n8k16 fragment order:
// uint idx = ((((ch*2+cbh)*6 + k16)*3 + tp)*32 + lane)*4 + q
//  q0/q1 = b0/b1 of tile 2tp, q2/q3 = tile 2tp+1 (b1 = +8 in k)
__device__ unsigned g_wH[4 * 2 * 6 * 3 * 32 * 4];       // 73.7 KB
__device__ unsigned g_bias2[4 * 3 * 49 * 28];           // half2 bias+mask, -1000 pad

__device__ __forceinline__ unsigned h2u(float a, float b) {
    __half2 h = __floats2half2_rn(a, b);
    return *reinterpret_cast<unsigned*>(&h);
}

__device__ __forceinline__ void mma16(float* c, unsigned a0, unsigned a1,
                                      unsigned a2, unsigned a3,
                                      unsigned b0, unsigned b1) {
    asm("mma.sync.aligned.m16n8k16.row.col.f32.f16.f16.f32 "
        "{%0,%1,%2,%3},{%4,%5,%6,%7},{%8,%9},{%0,%1,%2,%3};"
        : "+f"(c[0]), "+f"(c[1]), "+f"(c[2]), "+f"(c[3])
        : "r"(a0), "r"(a1), "r"(a2), "r"(a3), "r"(b0), "r"(b1));
}

__global__ void prep_tables(const float* __restrict__ qkv_w,
                            const float* __restrict__ proj_w,
                            const float* __restrict__ rel_table)
{
    int idx = blockIdx.x * blockDim.x + threadIdx.x;
    if (idx < 4 * 2 * 6 * 3 * 32 * 4) {
        int q    = idx & 3;
        int lane = (idx >> 2) & 31;
        int tp   = (idx >> 7) % 3;
        int k16  = (idx / 384) % 6;
        int cbh  = (idx / 2304) & 1;
        int ch   = idx / 4608;
        int g = lane >> 2, tg = lane & 3;
        int n = cbh * 48 + (2 * tp + (q >> 1)) * 8 + g;
        int k = k16 * 16 + 2 * tg + (q & 1) * 8;
        float lo = (ch < 3) ? qkv_w[(ch * 96 + n) * 96 + k]     : proj_w[n * 96 + k];
        float hi = (ch < 3) ? qkv_w[(ch * 96 + n) * 96 + k + 1] : proj_w[n * 96 + k + 1];
        g_wH[idx] = h2u(lo, hi);
    }
    if (idx < 4 * 3 * 49 * 28) {
        int jp = idx % 28;
        int i  = (idx / 28) % 49;
        int h  = (idx / 1372) % 3;
        int cls = idx / 4116;
        float v[2];
        #pragma unroll
        for (int s = 0; s < 2; ++s) {
            int j = 2 * jp + s;
            if (j < 49) {
                int yi = i / 7, xi = i - yi * 7, yj = j / 7, xj = j - yj * 7;
                float bias = rel_table[((yi - yj + 6) * 13 + (xi - xj + 6)) * 3 + h];
                int ri = ((cls & 2) ? (yi < 4 ? 1 : 2) : 0) * 3 + ((cls & 1) ? (xi < 4 ? 1 : 2) : 0);
                int rj = ((cls & 2) ? (yj < 4 ? 1 : 2) : 0) * 3 + ((cls & 1) ? (xj < 4 ? 1 : 2) : 0);
                if (ri != rj) bias -= 100.f;
                v[s] = bias;
            } else v[s] = -1000.f;   // exp -> exactly 0
        }
        g_bias2[idx] = h2u(v[0], v[1]);
    }
}

__global__ void __launch_bounds__(BT, 3)
swin_fused(const float* __restrict__ x,
           const float* __restrict__ ln_g, const float* __restrict__ ln_b,
           const float* __restrict__ qkv_b, const float* __restrict__ proj_b,
           float* __restrict__ out)
{
    extern __shared__ __align__(16) __half smh[];
    float* smf = reinterpret_cast<float*>(smh);

    const int tid  = threadIdx.x;
    const int lane = tid & 31;
    const int wrp  = tid >> 5;

    const int wid = blockIdx.x;
    const int b   = wid >> 6;
    const int w64 = wid & 63;
    const int wy  = w64 >> 3;
    const int wx  = w64 & 7;
    const int cls = ((wy == 7) ? 2 : 0) | ((wx == 7) ? 1 : 0);
    const float* xb = x + (size_t)b * C * HW * HW;

    const int rt  = wrp & 3;
    const int cbh = wrp >> 2;
    const int cb  = cbh * 48;
    const int g   = lane >> 2;
    const int tg  = lane & 3;
    const int ar0 = 16 * rt + g;          // A/C row 0 (row 1 = +8)
    const int rbase = 16 * rt + 8 * cbh;  // this warp's 8 owned rows

    // per-lane window-position offsets (computed once)
    int off0, off1;
    {
        int iy0 = lane / 7,  ix0 = lane - iy0 * 7;
        int p1  = lane + 32;
        int iy1 = p1 / 7,    ix1 = p1 - iy1 * 7;
        int h0 = wy * 7 + iy0 + SH; if (h0 >= HW) h0 -= HW;
        int w0 = wx * 7 + ix0 + SH; if (w0 >= HW) w0 -= HW;
        int h1 = wy * 7 + iy1 + SH; if (h1 >= HW) h1 -= HW;
        int w1 = wx * 7 + ix1 + SH; if (w1 >= HW) w1 -= HW;
        off0 = h0 * HW + w0;
        off1 = h1 * HW + w1;
    }
    const bool p1ok = (lane + 32) < 49;

    // ---- zero padding regions (before sync #1; V overwrites Vt col 48) ----
    for (int idx = tid; idx < 96 * 8; idx += BT) {    // Vt cols 48..63
        int d = idx >> 3, q = idx & 7;
        *(unsigned*)&smh[VTh + d * RVh + 48 + 2 * q] = 0;
    }
    for (int idx = tid; idx < 49 * 4; idx += BT) {    // SP cols 56..63
        int i = idx >> 2, q = idx & 3;
        *(unsigned*)&smh[SPh + i * RSh + 56 + 2 * q] = 0;
    }

    // ---- gather (roll folded in), fp32 -> fp16 ----
    {
        const float* bp = xb + (size_t)wrp * (HW * HW);
        #pragma unroll
        for (int k = 0; k < 12; ++k) {
            int c = wrp + 8 * k;
            smh[XWh + lane * RXh + c] = __float2half_rn(__ldg(bp + off0));
            if (p1ok) smh[XWh + (lane + 32) * RXh + c] = __float2half_rn(__ldg(bp + off1));
            bp += 8 * (HW * HW);
        }
    }
    __syncthreads();  // BLOCK: gather complete

    // ---- LayerNorm on warp's 8 owned rows ----
    {
        float g0 = __ldg(ln_g + lane),      b0 = __ldg(ln_b + lane);
        float g1 = __ldg(ln_g + lane + 32), b1 = __ldg(ln_b + lane + 32);
        float g2 = __ldg(ln_g + lane + 64), b2 = __ldg(ln_b + lane + 64);
        #pragma unroll 1
        for (int rr = 0; rr < 8; ++rr) {
            int p = rbase + rr;
            if (p < 49) {   // warp-uniform
                float v0 = __half2float(smh[XWh + p*RXh + lane]);
                float v1 = __half2float(smh[XWh + p*RXh + lane + 32]);
                float v2 = __half2float(smh[XWh + p*RXh + lane + 64]);
                float s = v0 + v1 + v2;
                #pragma unroll
                for (int o = 16; o; o >>= 1) s += __shfl_xor_sync(0xffffffffu, s, o);
                float mu = s * (1.f / 96.f);
                float d0 = v0 - mu, d1 = v1 - mu, d2 = v2 - mu;
                float vv = d0*d0 + d1*d1 + d2*d2;
                #pragma unroll
                for (int o = 16; o; o >>= 1) vv += __shfl_xor_sync(0xffffffffu, vv, o);
                float rstd = rsqrtf(vv * (1.f / 96.f) + 1e-5f);
                smh[XWh + p*RXh + lane]      = __float2half_rn(d0 * rstd * g0 + b0);
                smh[XWh + p*RXh + lane + 32] = __float2half_rn(d1 * rstd * g1 + b1);
                smh[XWh + p*RXh + lane + 64] = __float2half_rn(d2 * rstd * g2 + b2);
            }
        }
    }
    PAIRBAR();  // QKV mma A reads pair rows only (over-reads discarded)

    const float qscale = 0.17677669529663687f;  // 32^-0.5

    // ---- QKV GEMMs via fp16 m16n8k16 mma ----
    #pragma unroll 1
    for (int ch = 0; ch < 3; ++ch) {
        const uint4* wb4 = reinterpret_cast<const uint4*>(g_wH)
                           + ((ch * 2 + cbh) * 18) * 32 + lane;
        float acc[6][4];
        #pragma unroll
        for (int t = 0; t < 6; ++t)
            { acc[t][0]=0.f; acc[t][1]=0.f; acc[t][2]=0.f; acc[t][3]=0.f; }

        #pragma unroll 2
        for (int k16 = 0; k16 < 6; ++k16) {
            const __half* ab = &smh[XWh + ar0 * RXh + k16 * 16 + 2 * tg];
            unsigned a0 = *(const unsigned*)ab;
            unsigned a1 = *(const unsigned*)(ab + 8 * RXh);
            unsigned a2 = *(const unsigned*)(ab + 8);
            unsigned a3 = *(const unsigned*)(ab + 8 * RXh + 8);
            #pragma unroll
            for (int tp = 0; tp < 3; ++tp) {
                uint4 w = __ldg(wb4 + (k16 * 3 + tp) * 32);
                mma16(acc[2*tp],   a0, a1, a2, a3, w.x, w.y);
                mma16(acc[2*tp+1], a0, a1, a2, a3, w.z, w.w);
            }
        }

        if (ch == 0) {          // Q: scaled, fp16 into QO
            #pragma unroll
            for (int t = 0; t < 6; ++t) {
                int c0 = cb + 8 * t + 2 * tg;
                float2 bb = __ldg((const float2*)(qkv_b + c0));
                if (ar0 < 49)
                    *(unsigned*)&smh[QOh + ar0 * RXh + c0] =
                        h2u((acc[t][0] + bb.x) * qscale, (acc[t][1] + bb.y) * qscale);
                if (ar0 + 8 < 49)
                    *(unsigned*)&smh[QOh + (ar0+8) * RXh + c0] =
                        h2u((acc[t][2] + bb.x) * qscale, (acc[t][3] + bb.y) * qscale);
            }
        } else if (ch == 1) {   // K: row-major fp16 into KN
            #pragma unroll
            for (int t = 0; t < 6; ++t) {
                int c0 = cb + 8 * t + 2 * tg;
                float2 bb = __ldg((const float2*)(qkv_b + 96 + c0));
                if (ar0 < 49)
                    *(unsigned*)&smh[KNh + ar0 * RXh + c0] =
                        h2u(acc[t][0] + bb.x, acc[t][1] + bb.y);
                if (ar0 + 8 < 49)
                    *(unsigned*)&smh[KNh + (ar0+8) * RXh + c0] =
                        h2u(acc[t][2] + bb.x, acc[t][3] + bb.y);
            }
        } else {                // V: scatter transposed into Vt
            #pragma unroll
            for (int t = 0; t < 6; ++t) {
                int c0 = cb + 8 * t + 2 * tg;
                float2 bb = __ldg((const float2*)(qkv_b + 192 + c0));
                if (ar0 < 49) {
                    smh[VTh + c0 * RVh + ar0]       = __float2half_rn(acc[t][0] + bb.x);
                    smh[VTh + (c0+1) * RVh + ar0]   = __float2half_rn(acc[t][1] + bb.y);
                }
                if (ar0 + 8 < 49) {
                    smh[VTh + c0 * RVh + ar0+8]     = __float2half_rn(acc[t][2] + bb.x);
                    smh[VTh + (c0+1) * RVh + ar0+8] = __float2half_rn(acc[t][3] + bb.y);
                }
            }
        }
    }
    __syncthreads();  // BLOCK: Q, K, Vt published (B-operands cross pairs)

    // ---- attention per head: register softmax, pair barriers only ----
    #pragma unroll 1
    for (int h = 0; h < 3; ++h) {
        const int hb = h * 32;

        // QK A-fragments (Q, K-dim = 32 -> 2 k16 steps)
        unsigned qa[2][4];
        #pragma unroll
        for (int m = 0; m < 2; ++m) {
            const __half* ab = &smh[QOh + ar0 * RXh + hb + m * 16 + 2 * tg];
            qa[m][0] = *(const unsigned*)ab;
            qa[m][1] = *(const unsigned*)(ab + 8 * RXh);
            qa[m][2] = *(const unsigned*)(ab + 8);
            qa[m][3] = *(const unsigned*)(ab + 8 * RXh + 8);
        }
        const int ntiles = cbh ? 3 : 4;
        const int n8beg  = cbh ? 4 : 0;
        float ex[4][4];
        float s0 = 0.f, s1 = 0.f;
        const unsigned* bt2 = g_bias2 + (cls * 3 + h) * 49 * 28;
        const int bi0 = (ar0     < 49 ? ar0     : 48) * 28;
        const int bi1 = (ar0 + 8 < 49 ? ar0 + 8 : 48) * 28;

        #pragma unroll
        for (int tt = 0; tt < 4; ++tt) {
            if (tt < ntiles) {          // warp-uniform
                int n8 = n8beg + tt;
                float c[4] = {0.f, 0.f, 0.f, 0.f};
                const __half* kb = &smh[KNh + (8 * n8 + g) * RXh + hb + 2 * tg];
                mma16(c, qa[0][0], qa[0][1], qa[0][2], qa[0][3],
                      *(const unsigned*)kb, *(const unsigned*)(kb + 8));
                mma16(c, qa[1][0], qa[1][1], qa[1][2], qa[1][3],
                      *(const unsigned*)(kb + 16), *(const unsigned*)(kb + 24));
                int j0 = 8 * n8 + 2 * tg;
                unsigned u0 = __ldg(bt2 + bi0 + 4 * n8 + tg);
                unsigned u1 = __ldg(bt2 + bi1 + 4 * n8 + tg);
                float2 f0 = __half22float2(*(const __half2*)&u0);
                float2 f1 = __half22float2(*(const __half2*)&u1);
                // force e=0 for j>=49: garbage K rows can be NaN there
                ex[tt][0] = (j0     < 49) ? __expf(c[0] + f0.x) : 0.f;
                ex[tt][1] = (j0 + 1 < 49) ? __expf(c[1] + f0.y) : 0.f;
                ex[tt][2] = (j0     < 49) ? __expf(c[2] + f1.x) : 0.f;
                ex[tt][3] = (j0 + 1 < 49) ? __expf(c[3] + f1.y) : 0.f;
                s0 += ex[tt][0] + ex[tt][1];
                s1 += ex[tt][2] + ex[tt][3];
            } else {
                ex[tt][0] = ex[tt][1] = ex[tt][2] = ex[tt][3] = 0.f;
            }
        }
        // reduce across tg (lanes g*4 + tg)
        s0 += __shfl_xor_sync(0xffffffffu, s0, 1);
        s0 += __shfl_xor_sync(0xffffffffu, s0, 2);
        s1 += __shfl_xor_sync(0xffffffffu, s1, 1);
        s1 += __shfl_xor_sync(0xffffffffu, s1, 2);
        if (tg == 0) {
            smf[RSF + cbh * 64 + rt * 16 + g]     = s0;
            smf[RSF + cbh * 64 + rt * 16 + 8 + g] = s1;
        }
        PAIRBAR();  // rowsum exchange
        float inv0 = 1.f / (s0 + smf[RSF + (1 - cbh) * 64 + rt * 16 + g]);
        float inv1 = 1.f / (s1 + smf[RSF + (1 - cbh) * 64 + rt * 16 + 8 + g]);

        // write fp16 probs to SP (PV A layout); cols>=49 are zeros by e=0
        #pragma unroll
        for (int tt = 0; tt < 4; ++tt) {
            if (tt < ntiles) {
                int j0 = 8 * (n8beg + tt) + 2 * tg;
                if (ar0 < 49)
                    *(unsigned*)&smh[SPh + ar0 * RSh + j0] =
                        h2u(ex[tt][0] * inv0, ex[tt][1] * inv0);
                if (ar0 + 8 < 49)
                    *(unsigned*)&smh[SPh + (ar0+8) * RSh + j0] =
                        h2u(ex[tt][2] * inv1, ex[tt][3] * inv1);
            }
        }
        PAIRBAR();  // probs complete

        // O = P @ V : K-dim 56 -> 4 k16 steps (cols 49..63 zero)
        unsigned pa[4][4];
        #pragma unroll
        for (int m = 0; m < 4; ++m) {
            const __half* pb = &smh[SPh + ar0 * RSh + m * 16 + 2 * tg];
            pa[m][0] = *(const unsigned*)pb;
            pa[m][1] = *(const unsigned*)(pb + 8 * RSh);
            pa[m][2] = *(const unsigned*)(pb + 8);
            pa[m][3] = *(const unsigned*)(pb + 8 * RSh + 8);
        }
        #pragma unroll
        for (int nn = 0; nn < 2; ++nn) {
            int n8 = 2 * cbh + nn;
            float c[4] = {0.f, 0.f, 0.f, 0.f};
            const __half* vb = &smh[VTh + (hb + 8 * n8 + g) * RVh + 2 * tg];
            #pragma unroll
            for (int m = 0; m < 4; ++m)
                mma16(c, pa[m][0], pa[m][1], pa[m][2], pa[m][3],
                      *(const unsigned*)(vb + 16 * m), *(const unsigned*)(vb + 16 * m + 8));
            int d0 = hb + 8 * n8 + 2 * tg;
            if (ar0 < 49)
                *(unsigned*)&smh[QOh + ar0 * RXh + d0] = h2u(c[0], c[1]);
            if (ar0 + 8 < 49)
                *(unsigned*)&smh[QOh + (ar0+8) * RXh + d0] = h2u(c[2], c[3]);
        }
        PAIRBAR();  // pair done reading SP; next head may overwrite
    }
    __syncthreads();  // BLOCK: all pairs done reading KN/SP/Vt (staging reuses them)

    // ---- proj GEMM (fp16 mma), fp32 staging into dead KN/SP/Vt region ----
    {
        const uint4* wb4 = reinterpret_cast<const uint4*>(g_wH)
                           + ((3 * 2 + cbh) * 18) * 32 + lane;
        float acc[6][4];
        #pragma unroll
        for (int t = 0; t < 6; ++t)
            { acc[t][0]=0.f; acc[t][1]=0.f; acc[t][2]=0.f; acc[t][3]=0.f; }

        #pragma unroll 2
        for (int k16 = 0; k16 < 6; ++k16) {
            const __half* ab = &smh[QOh + ar0 * RXh + k16 * 16 + 2 * tg];
            unsigned a0 = *(const unsigned*)ab;
            unsigned a1 = *(const unsigned*)(ab + 8 * RXh);
            unsigned a2 = *(const unsigned*)(ab + 8);
            unsigned a3 = *(const unsigned*)(ab + 8 * RXh + 8);
            #pragma unroll
            for (int tp = 0; tp < 3; ++tp) {
                uint4 w = __ldg(wb4 + (k16 * 3 + tp) * 32);
                mma16(acc[2*tp],   a0, a1, a2, a3, w.x, w.y);
                mma16(acc[2*tp+1], a0, a1, a2, a3, w.z, w.w);
            }
        }

        #pragma unroll
        for (int t = 0; t < 6; ++t) {
            int c0 = cb + 8 * t + 2 * tg;
            float2 bb = __ldg((const float2*)(proj_b + c0));
            if (ar0 < 49)
                *(float2*)&smf[FSTf + ar0 * 100 + c0] =
                    make_float2(acc[t][0] + bb.x, acc[t][1] + bb.y);
            if (ar0 + 8 < 49)
                *(float2*)&smf[FSTf + (ar0+8) * 100 + c0] =
                    make_float2(acc[t][2] + bb.x, acc[t][3] + bb.y);
        }
    }
    __syncthreads();  // BLOCK: staging complete

    // ---- window reverse + unshift scatter (fp32 staging) ----
    {
        float* op = out + ((size_t)b * C + wrp) * (HW * HW);
        #pragma unroll
        for (int k = 0; k < 12; ++k) {
            int c = wrp + 8 * k;
            op[off0] = smf[FSTf + lane * 100 + c];
            if (p1ok) op[off1] = smf[FSTf + (lane + 32) * 100 + c];
            op += 8 * (HW * HW);
        }
    }
}

extern "C" void kernel_launch(void* const* d_in, const int* in_sizes, int n_in,
                              void* d_out, int out_size)
{
    const float* x      = (const float*)d_in[0];
    const float* ln_g   = (const float*)d_in[1];
    const float* ln_b   = (const float*)d_in[2];
    const float* qkv_w  = (const float*)d_in[3];
    const float* qkv_b  = (const float*)d_in[4];
    const float* proj_w = (const float*)d_in[5];
    const float* proj_b = (const float*)d_in[6];
    const float* rel    = (const float*)d_in[7];
    float* out = (float*)d_out;

    const int B = in_sizes[0] / (C * HW * HW);   // 128
    const size_t smem = (size_t)SMH * sizeof(__half);   // 53424 B

    prep_tables<<<144, 256>>>(qkv_w, proj_w, rel);

    cudaFuncSetAttribute(swin_fused, cudaFuncAttributeMaxDynamicSharedMemorySize, (int)smem);
    swin_fused<<<B * 64, BT, smem>>>(x, ln_g, ln_b, qkv_b, proj_b, out);
}